// round 2
// baseline (speedup 1.0000x reference)
#include <cuda_runtime.h>

#define NB 2
#define T  16
#define C  64
#define H  128
#define W  128
#define HW (H*W)

#define TH 8
#define TW 16

// ---------------- scratch (no allocation allowed) ----------------
__device__ float g_infeat[NB*C*HW];     // 1x1-conv output per step
__device__ float g_h1[NB*C*HW];         // conv1+leaky output per step
__device__ float g_wfc_t[3*C*C];        // [192][64]  (c-major, oc contiguous)
__device__ float g_w1_t[C*9*C];         // [(ci*9+k)][64]
__device__ float g_w2_t[C*9*C];

// ---------------- weight transposition ----------------
__global__ void k_prep(const float* __restrict__ Wfc,
                       const float* __restrict__ W1,
                       const float* __restrict__ W2) {
    int i = blockIdx.x * blockDim.x + threadIdx.x;
    if (i < 3*C*C) {                      // 12288
        int c = i >> 6, oc = i & 63;      // Wfc layout: [oc][3C][1][1]
        g_wfc_t[i] = Wfc[oc * (3*C) + c];
    }
    if (i < C*9*C) {                      // 36864
        int ck = i >> 6, oc = i & 63;
        int ci = ck / 9, k = ck % 9;      // W layout: [oc][ci][3][3]
        g_w1_t[i] = W1[(oc*C + ci)*9 + k];
        g_w2_t[i] = W2[(oc*C + ci)*9 + k];
    }
}

// ---------------- bilinear sampling helpers ----------------
struct Samp { int o00, o01, o10, o11; float w00, w01, w10, w11; };

__device__ __forceinline__ Samp make_samp(float gx, float gy) {
    float x0f = floorf(gx), y0f = floorf(gy);
    float wx = gx - x0f, wy = gy - y0f;
    int x0 = (int)x0f, y0 = (int)y0f;
    int x1 = x0 + 1,  y1 = y0 + 1;
    bool vx0 = (x0 >= 0) && (x0 < W), vx1 = (x1 >= 0) && (x1 < W);
    bool vy0 = (y0 >= 0) && (y0 < H), vy1 = (y1 >= 0) && (y1 < H);
    int cx0 = min(max(x0, 0), W-1), cx1 = min(max(x1, 0), W-1);
    int cy0 = min(max(y0, 0), H-1), cy1 = min(max(y1, 0), H-1);
    Samp s;
    s.o00 = cy0*W + cx0; s.o01 = cy0*W + cx1;
    s.o10 = cy1*W + cx0; s.o11 = cy1*W + cx1;
    s.w00 = (vx0 && vy0) ? (1.f-wx)*(1.f-wy) : 0.f;
    s.w01 = (vx1 && vy0) ? wx*(1.f-wy)       : 0.f;
    s.w10 = (vx0 && vy1) ? (1.f-wx)*wy       : 0.f;
    s.w11 = (vx1 && vy1) ? wx*wy             : 0.f;
    return s;
}

__device__ __forceinline__ float bsample(const float* __restrict__ p, const Samp& s) {
    return p[s.o00]*s.w00 + p[s.o01]*s.w01 + p[s.o10]*s.w10 + p[s.o11]*s.w11;
}

// ---------------- kernel 1: flow warps + 1x1 conv (192->64) ----------------
// comb = [a2, a1, x];  infeat = Wfc @ comb + bfc
__global__ __launch_bounds__(W) void k_warp_fc(
    const float* __restrict__ feats, const float* __restrict__ flows,
    const float* __restrict__ out,   const float* __restrict__ bfc, int t)
{
    int b = blockIdx.x;
    int n = b >> 7, y = b & 127, x = threadIdx.x;
    int pix = y * W + x;

    const float* y1p = (t >= 1) ? out   + (size_t)(n*T + (t-1)) * C * HW
                                : feats + (size_t)(n*T)         * C * HW;
    const float* y2p = (t >= 2) ? out   + (size_t)(n*T + (t-2)) * C * HW
                                : feats + (size_t)(n*T)         * C * HW;
    const float* xp  = feats + (size_t)(n*T + t) * C * HW + pix;

    float f1x = 0.f, f1y = 0.f;
    if (t >= 1) {
        const float* f1p = flows + (size_t)(n*T + (t-1)) * 2 * HW;
        f1x = f1p[pix]; f1y = f1p[HW + pix];
    }
    Samp s1 = make_samp((float)x + f1x, (float)y + f1y);

    float f2cx = f1x, f2cy = f1y;       // t<2: f2=0 -> warp(f2)=0 -> f2c=f1
    if (t >= 2) {
        const float* f2p = flows + (size_t)(n*T + (t-2)) * 2 * HW;
        f2cx += bsample(f2p,      s1);
        f2cy += bsample(f2p + HW, s1);
    }
    Samp s2 = make_samp((float)x + f2cx, (float)y + f2cy);

    float4 acc[16];
    #pragma unroll
    for (int j = 0; j < 16; j++) acc[j] = __ldg((const float4*)bfc + j);

    #pragma unroll 2
    for (int ci = 0; ci < C; ci++) {
        float a1 = bsample(y1p + ci*HW, s1);
        float a2 = bsample(y2p + ci*HW, s2);
        float xv = xp[ci*HW];
        const float4* wa2 = (const float4*)(g_wfc_t + (size_t)ci       * C);
        const float4* wa1 = (const float4*)(g_wfc_t + (size_t)(C+ci)   * C);
        const float4* wxr = (const float4*)(g_wfc_t + (size_t)(2*C+ci) * C);
        #pragma unroll
        for (int j = 0; j < 16; j++) {
            float4 w2v = __ldg(&wa2[j]);
            float4 w1v = __ldg(&wa1[j]);
            float4 wxv = __ldg(&wxr[j]);
            acc[j].x += a2*w2v.x + a1*w1v.x + xv*wxv.x;
            acc[j].y += a2*w2v.y + a1*w1v.y + xv*wxv.y;
            acc[j].z += a2*w2v.z + a1*w1v.z + xv*wxv.z;
            acc[j].w += a2*w2v.w + a1*w1v.w + xv*wxv.w;
        }
    }

    float* op = g_infeat + (size_t)n * C * HW + pix;
    #pragma unroll
    for (int j = 0; j < 16; j++) {
        op[(4*j+0)*HW] = acc[j].x;
        op[(4*j+1)*HW] = acc[j].y;
        op[(4*j+2)*HW] = acc[j].z;
        op[(4*j+3)*HW] = acc[j].w;
    }
}

// ---------------- kernels 2/3: 3x3 conv, 64->64, SAME, zero pad ----------------
// phase 0: g_infeat -> leaky_relu -> g_h1   (weights g_w1_t, bias b1)
// phase 1: g_h1 -> + feats[t] -> d_out[t]   (weights g_w2_t, bias b2)
__global__ __launch_bounds__(TH*TW, 4) void k_conv3(
    float* __restrict__ outp, const float* __restrict__ bias,
    const float* __restrict__ feats, int phase, int t)
{
    __shared__ float s[C][TH+2][TW+2];
    int n   = blockIdx.z;
    int gx0 = blockIdx.x * TW - 1;
    int gy0 = blockIdx.y * TH - 1;
    int tid = threadIdx.x;

    const float* inb = (phase ? g_h1 : g_infeat) + (size_t)n * C * HW;

    for (int i = tid; i < C*(TH+2)*(TW+2); i += TH*TW) {
        int ci = i / ((TH+2)*(TW+2));
        int r  = i % ((TH+2)*(TW+2));
        int ry = r / (TW+2), rx = r % (TW+2);
        int gy = gy0 + ry, gx = gx0 + rx;
        float v = 0.f;
        if (gy >= 0 && gy < H && gx >= 0 && gx < W) v = inb[ci*HW + gy*W + gx];
        s[ci][ry][rx] = v;
    }
    __syncthreads();

    int tx = tid % TW, ty = tid / TW;
    const float* wt = phase ? g_w2_t : g_w1_t;

    float4 acc[16];
    #pragma unroll
    for (int j = 0; j < 16; j++) acc[j] = __ldg((const float4*)bias + j);

    for (int ci = 0; ci < C; ci++) {
        float v[9];
        #pragma unroll
        for (int ky = 0; ky < 3; ky++)
            #pragma unroll
            for (int kx = 0; kx < 3; kx++)
                v[ky*3 + kx] = s[ci][ty+ky][tx+kx];
        #pragma unroll
        for (int k = 0; k < 9; k++) {
            const float4* wr = (const float4*)(wt + (size_t)(ci*9 + k) * C);
            float vk = v[k];
            #pragma unroll
            for (int j = 0; j < 16; j++) {
                float4 wv = __ldg(&wr[j]);
                acc[j].x += vk*wv.x; acc[j].y += vk*wv.y;
                acc[j].z += vk*wv.z; acc[j].w += vk*wv.w;
            }
        }
    }

    int y = gy0 + 1 + ty, x = gx0 + 1 + tx;
    int pix = y * W + x;

    if (phase == 0) {
        float* op = g_h1 + (size_t)n * C * HW + pix;
        #pragma unroll
        for (int j = 0; j < 16; j++) {
            float4 a = acc[j];
            op[(4*j+0)*HW] = a.x > 0.f ? a.x : 0.1f*a.x;
            op[(4*j+1)*HW] = a.y > 0.f ? a.y : 0.1f*a.y;
            op[(4*j+2)*HW] = a.z > 0.f ? a.z : 0.1f*a.z;
            op[(4*j+3)*HW] = a.w > 0.f ? a.w : 0.1f*a.w;
        }
    } else {
        const float* res = feats + (size_t)(n*T + t) * C * HW + pix;
        float*       op  = outp  + (size_t)(n*T + t) * C * HW + pix;
        #pragma unroll
        for (int j = 0; j < 16; j++) {
            float4 a = acc[j];
            op[(4*j+0)*HW] = a.x + res[(4*j+0)*HW];
            op[(4*j+1)*HW] = a.y + res[(4*j+1)*HW];
            op[(4*j+2)*HW] = a.z + res[(4*j+2)*HW];
            op[(4*j+3)*HW] = a.w + res[(4*j+3)*HW];
        }
    }
}

// ---------------- launch ----------------
extern "C" void kernel_launch(void* const* d_in, const int* in_sizes, int n_in,
                              void* d_out, int out_size) {
    const float* feats = (const float*)d_in[0];
    const float* flows = (const float*)d_in[1];
    const float* bfc   = (const float*)d_in[3];
    const float* b1    = (const float*)d_in[5];
    const float* b2    = (const float*)d_in[7];
    float* out = (float*)d_out;
    (void)in_sizes; (void)n_in; (void)out_size;

    k_prep<<<(C*9*C + 255)/256, 256>>>((const float*)d_in[2],
                                       (const float*)d_in[4],
                                       (const float*)d_in[6]);

    dim3 cgrid(W/TW, H/TH, NB);
    for (int t = 0; t < T; t++) {
        k_warp_fc<<<NB*H, W>>>(feats, flows, out, bfc, t);
        k_conv3<<<cgrid, TH*TW>>>(out, b1, feats, 0, t);
        k_conv3<<<cgrid, TH*TW>>>(out, b2, feats, 1, t);
    }
}

// round 3
// speedup vs baseline: 1.1742x; 1.1742x over previous
#include <cuda_runtime.h>

#define NB 2
#define T  16
#define C  64
#define H  128
#define W  128
#define HW (H*W)

#define CTW 16
#define CTH 16
#define CCH 32   // ci chunk held in smem

// ---------------- scratch (no allocation allowed) ----------------
__device__ float g_comb[NB*2*C*HW];     // [n][a2:0-63 | a1:64-127][HW]
__device__ float g_infeat[NB*C*HW];     // 1x1-conv output per step
__device__ float g_h1[NB*C*HW];         // conv1+leaky output per step
__device__ float g_wfc_t[3*C*C];        // [192][64]  (c-major, oc contiguous)
__device__ float g_w1_t[C*9*C];         // [(ci*9+k)][64]
__device__ float g_w2_t[C*9*C];

// ---------------- weight transposition ----------------
__global__ void k_prep(const float* __restrict__ Wfc,
                       const float* __restrict__ W1,
                       const float* __restrict__ W2) {
    int i = blockIdx.x * blockDim.x + threadIdx.x;
    if (i < 3*C*C) {                      // 12288
        int c = i >> 6, oc = i & 63;      // Wfc layout: [oc][3C]
        g_wfc_t[i] = Wfc[oc * (3*C) + c];
    }
    if (i < C*9*C) {                      // 36864
        int ck = i >> 6, oc = i & 63;
        int ci = ck / 9, k = ck % 9;      // W layout: [oc][ci][3][3]
        g_w1_t[i] = W1[(oc*C + ci)*9 + k];
        g_w2_t[i] = W2[(oc*C + ci)*9 + k];
    }
}

// ---------------- bilinear sampling helpers ----------------
struct Samp { int o00, o01, o10, o11; float w00, w01, w10, w11; };

__device__ __forceinline__ Samp make_samp(float gx, float gy) {
    float x0f = floorf(gx), y0f = floorf(gy);
    float wx = gx - x0f, wy = gy - y0f;
    int x0 = (int)x0f, y0 = (int)y0f;
    int x1 = x0 + 1,  y1 = y0 + 1;
    bool vx0 = (x0 >= 0) && (x0 < W), vx1 = (x1 >= 0) && (x1 < W);
    bool vy0 = (y0 >= 0) && (y0 < H), vy1 = (y1 >= 0) && (y1 < H);
    int cx0 = min(max(x0, 0), W-1), cx1 = min(max(x1, 0), W-1);
    int cy0 = min(max(y0, 0), H-1), cy1 = min(max(y1, 0), H-1);
    Samp s;
    s.o00 = cy0*W + cx0; s.o01 = cy0*W + cx1;
    s.o10 = cy1*W + cx0; s.o11 = cy1*W + cx1;
    s.w00 = (vx0 && vy0) ? (1.f-wx)*(1.f-wy) : 0.f;
    s.w01 = (vx1 && vy0) ? wx*(1.f-wy)       : 0.f;
    s.w10 = (vx0 && vy1) ? (1.f-wx)*wy       : 0.f;
    s.w11 = (vx1 && vy1) ? wx*wy             : 0.f;
    return s;
}

__device__ __forceinline__ float bsample(const float* __restrict__ p, const Samp& s) {
    return p[s.o00]*s.w00 + p[s.o01]*s.w01 + p[s.o10]*s.w10 + p[s.o11]*s.w11;
}

// ---------------- kernel 1a: flow warps -> g_comb ----------------
// grid (NB*H, 4 ci-groups), block 128
__global__ __launch_bounds__(128) void k_warp(
    const float* __restrict__ feats, const float* __restrict__ flows,
    const float* __restrict__ out, int t)
{
    int bx = blockIdx.x;
    int n = bx >> 7, y = bx & 127, x = threadIdx.x;
    int cig = blockIdx.y;                 // 16 channels per group
    int pix = y * W + x;

    const float* y1p = (t >= 1) ? out   + (size_t)(n*T + (t-1)) * C * HW
                                : feats + (size_t)(n*T)         * C * HW;
    const float* y2p = (t >= 2) ? out   + (size_t)(n*T + (t-2)) * C * HW
                                : feats + (size_t)(n*T)         * C * HW;

    float f1x = 0.f, f1y = 0.f;
    if (t >= 1) {
        const float* f1p = flows + (size_t)(n*T + (t-1)) * 2 * HW;
        f1x = f1p[pix]; f1y = f1p[HW + pix];
    }
    Samp s1 = make_samp((float)x + f1x, (float)y + f1y);

    float f2cx = f1x, f2cy = f1y;         // t<2: f2=0 -> warp(f2)=0 -> f2c=f1
    if (t >= 2) {
        const float* f2p = flows + (size_t)(n*T + (t-2)) * 2 * HW;
        f2cx += bsample(f2p,      s1);
        f2cy += bsample(f2p + HW, s1);
    }
    Samp s2 = make_samp((float)x + f2cx, (float)y + f2cy);

    float* a2o = g_comb + (size_t)n * 2*C*HW + pix;          // ch 0..63
    float* a1o = a2o + (size_t)C*HW;                         // ch 64..127

    int c0 = cig * 16;
    #pragma unroll 4
    for (int ci = c0; ci < c0 + 16; ci++) {
        a2o[ci*HW] = bsample(y2p + ci*HW, s2);
        a1o[ci*HW] = bsample(y1p + ci*HW, s1);
    }
}

// ---------------- kernel 1b: 1x1 conv 192->64 ----------------
// grid (NB*H, 4 oc-groups), block 128; each thread 1 pixel x 16 oc
__global__ __launch_bounds__(128) void k_fc(
    const float* __restrict__ feats, const float* __restrict__ bfc, int t)
{
    int bx = blockIdx.x;
    int n = bx >> 7, y = bx & 127, x = threadIdx.x;
    int ocg = blockIdx.y;
    int pix = y * W + x;

    const float* cb = g_comb + (size_t)n * 2*C*HW + pix;               // 128 ch
    const float* xb = feats + (size_t)(n*T + t) * C * HW + pix;        // 64 ch

    float4 acc[4];
    #pragma unroll
    for (int j = 0; j < 4; j++) acc[j] = __ldg((const float4*)bfc + ocg*4 + j);

    #pragma unroll 4
    for (int c = 0; c < 2*C; c++) {
        float v = cb[c*HW];
        const float4* wr = (const float4*)(g_wfc_t + (size_t)c * C) + ocg*4;
        #pragma unroll
        for (int j = 0; j < 4; j++) {
            float4 w = __ldg(&wr[j]);
            acc[j].x += v*w.x; acc[j].y += v*w.y;
            acc[j].z += v*w.z; acc[j].w += v*w.w;
        }
    }
    #pragma unroll 4
    for (int c = 0; c < C; c++) {
        float v = xb[c*HW];
        const float4* wr = (const float4*)(g_wfc_t + (size_t)(2*C + c) * C) + ocg*4;
        #pragma unroll
        for (int j = 0; j < 4; j++) {
            float4 w = __ldg(&wr[j]);
            acc[j].x += v*w.x; acc[j].y += v*w.y;
            acc[j].z += v*w.z; acc[j].w += v*w.w;
        }
    }

    float* op = g_infeat + (size_t)n * C * HW + pix + (size_t)(ocg*16)*HW;
    #pragma unroll
    for (int j = 0; j < 4; j++) {
        op[(4*j+0)*HW] = acc[j].x;
        op[(4*j+1)*HW] = acc[j].y;
        op[(4*j+2)*HW] = acc[j].z;
        op[(4*j+3)*HW] = acc[j].w;
    }
}

// ---------------- kernels 2/3: 3x3 conv, 64->64, SAME, zero pad ----------------
// grid (8, 8, NB*4), block 256 (16x16 tile); thread = 1 pixel x 16 oc
// phase 0: g_infeat -> leaky_relu -> g_h1
// phase 1: g_h1 -> + feats[t] -> d_out[t]
__global__ __launch_bounds__(256, 3) void k_conv3(
    float* __restrict__ outp, const float* __restrict__ bias,
    const float* __restrict__ feats, int phase, int t)
{
    __shared__ float s[CCH][CTH+2][CTW+2];     // 32*18*18*4 = 41472 B
    int n   = blockIdx.z >> 2;
    int ocg = blockIdx.z & 3;
    int gx0 = blockIdx.x * CTW - 1;
    int gy0 = blockIdx.y * CTH - 1;
    int tid = threadIdx.x;
    int tx = tid & 15, ty = tid >> 4;

    const float* inb = (phase ? g_h1 : g_infeat) + (size_t)n * C * HW;
    const float* wt  = phase ? g_w2_t : g_w1_t;

    float4 acc[4];
    #pragma unroll
    for (int j = 0; j < 4; j++) acc[j] = __ldg((const float4*)bias + ocg*4 + j);

    for (int cc = 0; cc < C; cc += CCH) {
        if (cc) __syncthreads();
        for (int i = tid; i < CCH*(CTH+2)*(CTW+2); i += 256) {
            int ci = i / ((CTH+2)*(CTW+2));
            int r  = i % ((CTH+2)*(CTW+2));
            int ry = r / (CTW+2), rx = r % (CTW+2);
            int gy = gy0 + ry, gx = gx0 + rx;
            float v = 0.f;
            if (gy >= 0 && gy < H && gx >= 0 && gx < W)
                v = inb[(cc+ci)*HW + gy*W + gx];
            s[ci][ry][rx] = v;
        }
        __syncthreads();

        for (int ci = 0; ci < CCH; ci++) {
            float v[9];
            #pragma unroll
            for (int ky = 0; ky < 3; ky++)
                #pragma unroll
                for (int kx = 0; kx < 3; kx++)
                    v[ky*3 + kx] = s[ci][ty+ky][tx+kx];
            #pragma unroll
            for (int k = 0; k < 9; k++) {
                const float4* wr = (const float4*)(wt + (size_t)((cc+ci)*9 + k) * C) + ocg*4;
                float vk = v[k];
                #pragma unroll
                for (int j = 0; j < 4; j++) {
                    float4 w = __ldg(&wr[j]);
                    acc[j].x += vk*w.x; acc[j].y += vk*w.y;
                    acc[j].z += vk*w.z; acc[j].w += vk*w.w;
                }
            }
        }
    }

    int y = gy0 + 1 + ty, x = gx0 + 1 + tx;
    int pix = y * W + x;

    if (phase == 0) {
        float* op = g_h1 + (size_t)n * C * HW + pix + (size_t)(ocg*16)*HW;
        #pragma unroll
        for (int j = 0; j < 4; j++) {
            float4 a = acc[j];
            op[(4*j+0)*HW] = a.x > 0.f ? a.x : 0.1f*a.x;
            op[(4*j+1)*HW] = a.y > 0.f ? a.y : 0.1f*a.y;
            op[(4*j+2)*HW] = a.z > 0.f ? a.z : 0.1f*a.z;
            op[(4*j+3)*HW] = a.w > 0.f ? a.w : 0.1f*a.w;
        }
    } else {
        size_t base = (size_t)(n*T + t) * C * HW + pix + (size_t)(ocg*16)*HW;
        const float* res = feats + base;
        float*       op  = outp  + base;
        #pragma unroll
        for (int j = 0; j < 4; j++) {
            float4 a = acc[j];
            op[(4*j+0)*HW] = a.x + res[(4*j+0)*HW];
            op[(4*j+1)*HW] = a.y + res[(4*j+1)*HW];
            op[(4*j+2)*HW] = a.z + res[(4*j+2)*HW];
            op[(4*j+3)*HW] = a.w + res[(4*j+3)*HW];
        }
    }
}

// ---------------- launch ----------------
extern "C" void kernel_launch(void* const* d_in, const int* in_sizes, int n_in,
                              void* d_out, int out_size) {
    const float* feats = (const float*)d_in[0];
    const float* flows = (const float*)d_in[1];
    const float* bfc   = (const float*)d_in[3];
    const float* b1    = (const float*)d_in[5];
    const float* b2    = (const float*)d_in[7];
    float* out = (float*)d_out;
    (void)in_sizes; (void)n_in; (void)out_size;

    k_prep<<<(C*9*C + 255)/256, 256>>>((const float*)d_in[2],
                                       (const float*)d_in[4],
                                       (const float*)d_in[6]);

    dim3 wgrid(NB*H, 4);
    dim3 cgrid(W/CTW, H/CTH, NB*4);
    for (int t = 0; t < T; t++) {
        k_warp<<<wgrid, 128>>>(feats, flows, out, t);
        k_fc<<<wgrid, 128>>>(feats, bfc, t);
        k_conv3<<<cgrid, 256>>>(out, b1, feats, 0, t);
        k_conv3<<<cgrid, 256>>>(out, b2, feats, 1, t);
    }
}

// round 4
// speedup vs baseline: 1.6443x; 1.4004x over previous
#include <cuda_runtime.h>

#define NB 2
#define T  16
#define C  64
#define H  128
#define W  128
#define HW (H*W)

#define CH2 16   // ci chunk held in smem (conv3)

// ---------------- scratch (no allocation allowed) ----------------
__device__ float g_comb[NB*2*C*HW];     // [n][a2:0-63 | a1:64-127][HW]
__device__ float g_infeat[NB*C*HW];     // 1x1-conv output per step
__device__ float g_h1[NB*C*HW];         // conv1+leaky output per step
__device__ float g_wfc_t[3*C*C];        // [192][64]  (c-major, oc contiguous)
__device__ float g_w1_t[C*9*C];         // [(ci*9+k)][64]
__device__ float g_w2_t[C*9*C];

// ---------------- weight transposition ----------------
__global__ void k_prep(const float* __restrict__ Wfc,
                       const float* __restrict__ W1,
                       const float* __restrict__ W2) {
    int i = blockIdx.x * blockDim.x + threadIdx.x;
    if (i < 3*C*C) {                      // 12288
        int c = i >> 6, oc = i & 63;      // Wfc layout: [oc][3C]
        g_wfc_t[i] = Wfc[oc * (3*C) + c];
    }
    if (i < C*9*C) {                      // 36864
        int ck = i >> 6, oc = i & 63;
        int ci = ck / 9, k = ck % 9;      // W layout: [oc][ci][3][3]
        g_w1_t[i] = W1[(oc*C + ci)*9 + k];
        g_w2_t[i] = W2[(oc*C + ci)*9 + k];
    }
}

// ---------------- bilinear sampling helpers ----------------
struct Samp { int o00, o01, o10, o11; float w00, w01, w10, w11; };

__device__ __forceinline__ Samp make_samp(float gx, float gy) {
    float x0f = floorf(gx), y0f = floorf(gy);
    float wx = gx - x0f, wy = gy - y0f;
    int x0 = (int)x0f, y0 = (int)y0f;
    int x1 = x0 + 1,  y1 = y0 + 1;
    bool vx0 = (x0 >= 0) && (x0 < W), vx1 = (x1 >= 0) && (x1 < W);
    bool vy0 = (y0 >= 0) && (y0 < H), vy1 = (y1 >= 0) && (y1 < H);
    int cx0 = min(max(x0, 0), W-1), cx1 = min(max(x1, 0), W-1);
    int cy0 = min(max(y0, 0), H-1), cy1 = min(max(y1, 0), H-1);
    Samp s;
    s.o00 = cy0*W + cx0; s.o01 = cy0*W + cx1;
    s.o10 = cy1*W + cx0; s.o11 = cy1*W + cx1;
    s.w00 = (vx0 && vy0) ? (1.f-wx)*(1.f-wy) : 0.f;
    s.w01 = (vx1 && vy0) ? wx*(1.f-wy)       : 0.f;
    s.w10 = (vx0 && vy1) ? (1.f-wx)*wy       : 0.f;
    s.w11 = (vx1 && vy1) ? wx*wy             : 0.f;
    return s;
}

__device__ __forceinline__ float bsample(const float* __restrict__ p, const Samp& s) {
    return p[s.o00]*s.w00 + p[s.o01]*s.w01 + p[s.o10]*s.w10 + p[s.o11]*s.w11;
}

// ---------------- kernel 1a: flow warps -> g_comb ----------------
// grid (NB*H, 4 ci-groups), block 128
__global__ __launch_bounds__(128) void k_warp(
    const float* __restrict__ feats, const float* __restrict__ flows,
    const float* __restrict__ out, int t)
{
    int bx = blockIdx.x;
    int n = bx >> 7, y = bx & 127, x = threadIdx.x;
    int cig = blockIdx.y;                 // 16 channels per group
    int pix = y * W + x;

    const float* y1p = (t >= 1) ? out   + (size_t)(n*T + (t-1)) * C * HW
                                : feats + (size_t)(n*T)         * C * HW;
    const float* y2p = (t >= 2) ? out   + (size_t)(n*T + (t-2)) * C * HW
                                : feats + (size_t)(n*T)         * C * HW;

    float f1x = 0.f, f1y = 0.f;
    if (t >= 1) {
        const float* f1p = flows + (size_t)(n*T + (t-1)) * 2 * HW;
        f1x = f1p[pix]; f1y = f1p[HW + pix];
    }
    Samp s1 = make_samp((float)x + f1x, (float)y + f1y);

    float f2cx = f1x, f2cy = f1y;         // t<2: f2=0 -> warp(f2)=0 -> f2c=f1
    if (t >= 2) {
        const float* f2p = flows + (size_t)(n*T + (t-2)) * 2 * HW;
        f2cx += bsample(f2p,      s1);
        f2cy += bsample(f2p + HW, s1);
    }
    Samp s2 = make_samp((float)x + f2cx, (float)y + f2cy);

    float* a2o = g_comb + (size_t)n * 2*C*HW + pix;          // ch 0..63
    float* a1o = a2o + (size_t)C*HW;                         // ch 64..127

    int c0 = cig * 16;
    #pragma unroll 4
    for (int ci = c0; ci < c0 + 16; ci++) {
        a2o[ci*HW] = bsample(y2p + ci*HW, s2);
        a1o[ci*HW] = bsample(y1p + ci*HW, s1);
    }
}

// ---------------- kernel 1b: 1x1 conv 192->64, 2 pixels/thread ----------------
// grid (NB*64, 4 oc-groups), block 128; thread handles rows y and y+64
__global__ __launch_bounds__(128) void k_fc(
    const float* __restrict__ feats, const float* __restrict__ bfc, int t)
{
    int bx = blockIdx.x;
    int n = bx >> 6, y = bx & 63, x = threadIdx.x;
    int ocg = blockIdx.y;
    int pix0 = y * W + x;
    int pix1 = (y + 64) * W + x;

    const float* cb = g_comb + (size_t)n * 2*C*HW;                     // 128 ch
    const float* xb = feats + (size_t)(n*T + t) * C * HW;              // 64 ch

    float4 acc0[4], acc1[4];
    #pragma unroll
    for (int j = 0; j < 4; j++) {
        acc0[j] = __ldg((const float4*)bfc + ocg*4 + j);
        acc1[j] = acc0[j];
    }

    #pragma unroll 2
    for (int c = 0; c < 2*C; c++) {
        float v0 = cb[c*HW + pix0];
        float v1 = cb[c*HW + pix1];
        const float4* wr = (const float4*)(g_wfc_t + (size_t)c * C) + ocg*4;
        #pragma unroll
        for (int j = 0; j < 4; j++) {
            float4 w = __ldg(&wr[j]);
            acc0[j].x += v0*w.x; acc0[j].y += v0*w.y;
            acc0[j].z += v0*w.z; acc0[j].w += v0*w.w;
            acc1[j].x += v1*w.x; acc1[j].y += v1*w.y;
            acc1[j].z += v1*w.z; acc1[j].w += v1*w.w;
        }
    }
    #pragma unroll 2
    for (int c = 0; c < C; c++) {
        float v0 = xb[c*HW + pix0];
        float v1 = xb[c*HW + pix1];
        const float4* wr = (const float4*)(g_wfc_t + (size_t)(2*C + c) * C) + ocg*4;
        #pragma unroll
        for (int j = 0; j < 4; j++) {
            float4 w = __ldg(&wr[j]);
            acc0[j].x += v0*w.x; acc0[j].y += v0*w.y;
            acc0[j].z += v0*w.z; acc0[j].w += v0*w.w;
            acc1[j].x += v1*w.x; acc1[j].y += v1*w.y;
            acc1[j].z += v1*w.z; acc1[j].w += v1*w.w;
        }
    }

    float* ob = g_infeat + (size_t)n * C * HW + (size_t)(ocg*16)*HW;
    #pragma unroll
    for (int j = 0; j < 4; j++) {
        ob[(4*j+0)*HW + pix0] = acc0[j].x;
        ob[(4*j+1)*HW + pix0] = acc0[j].y;
        ob[(4*j+2)*HW + pix0] = acc0[j].z;
        ob[(4*j+3)*HW + pix0] = acc0[j].w;
        ob[(4*j+0)*HW + pix1] = acc1[j].x;
        ob[(4*j+1)*HW + pix1] = acc1[j].y;
        ob[(4*j+2)*HW + pix1] = acc1[j].z;
        ob[(4*j+3)*HW + pix1] = acc1[j].w;
    }
}

// ---------------- kernels 2/3: 3x3 conv, 64->64, SAME, zero pad ----------------
// grid (8, 8, NB*4), block 128 (16x8); thread = vertical pixel pair x 16 oc
// phase 0: g_infeat -> leaky_relu -> g_h1
// phase 1: g_h1 -> + feats[t] -> d_out[t]
__global__ __launch_bounds__(128, 5) void k_conv3(
    float* __restrict__ outp, const float* __restrict__ bias,
    const float* __restrict__ feats, int phase, int t)
{
    __shared__ float s[CH2][18][18];           // 16*18*18*4 = 20736 B
    int n   = blockIdx.z >> 2;
    int ocg = blockIdx.z & 3;
    int gx0 = blockIdx.x * 16 - 1;
    int gy0 = blockIdx.y * 16 - 1;
    int tid = threadIdx.x;
    int tx = tid & 15, ty = tid >> 4;          // ty: 0..7 -> rows 2ty, 2ty+1

    const float* inb = (phase ? g_h1 : g_infeat) + (size_t)n * C * HW;
    const float* wt  = phase ? g_w2_t : g_w1_t;

    float4 acc0[4], acc1[4];
    #pragma unroll
    for (int j = 0; j < 4; j++) {
        acc0[j] = __ldg((const float4*)bias + ocg*4 + j);
        acc1[j] = acc0[j];
    }

    for (int cc = 0; cc < C; cc += CH2) {
        if (cc) __syncthreads();
        for (int i = tid; i < CH2*18*18; i += 128) {
            int ci = i / (18*18);
            int r  = i % (18*18);
            int ry = r / 18, rx = r % 18;
            int gy = gy0 + ry, gx = gx0 + rx;
            float v = 0.f;
            if (gy >= 0 && gy < H && gx >= 0 && gx < W)
                v = inb[(cc+ci)*HW + gy*W + gx];
            s[ci][ry][rx] = v;
        }
        __syncthreads();

        for (int ci = 0; ci < CH2; ci++) {
            float v[4][3];                     // rows 2ty..2ty+3, cols tx..tx+2
            #pragma unroll
            for (int r = 0; r < 4; r++)
                #pragma unroll
                for (int c3 = 0; c3 < 3; c3++)
                    v[r][c3] = s[ci][2*ty + r][tx + c3];
            #pragma unroll
            for (int ky = 0; ky < 3; ky++) {
                #pragma unroll
                for (int kx = 0; kx < 3; kx++) {
                    const float4* wr =
                        (const float4*)(wt + (size_t)((cc+ci)*9 + ky*3 + kx) * C) + ocg*4;
                    float vk0 = v[ky][kx];
                    float vk1 = v[ky+1][kx];
                    #pragma unroll
                    for (int j = 0; j < 4; j++) {
                        float4 w = __ldg(&wr[j]);
                        acc0[j].x += vk0*w.x; acc0[j].y += vk0*w.y;
                        acc0[j].z += vk0*w.z; acc0[j].w += vk0*w.w;
                        acc1[j].x += vk1*w.x; acc1[j].y += vk1*w.y;
                        acc1[j].z += vk1*w.z; acc1[j].w += vk1*w.w;
                    }
                }
            }
        }
    }

    int y0 = gy0 + 1 + 2*ty, x = gx0 + 1 + tx;
    int p0 = y0 * W + x;
    int p1 = p0 + W;

    if (phase == 0) {
        float* ob = g_h1 + (size_t)n * C * HW + (size_t)(ocg*16)*HW;
        #pragma unroll
        for (int j = 0; j < 4; j++) {
            float4 a = acc0[j], b = acc1[j];
            ob[(4*j+0)*HW + p0] = a.x > 0.f ? a.x : 0.1f*a.x;
            ob[(4*j+1)*HW + p0] = a.y > 0.f ? a.y : 0.1f*a.y;
            ob[(4*j+2)*HW + p0] = a.z > 0.f ? a.z : 0.1f*a.z;
            ob[(4*j+3)*HW + p0] = a.w > 0.f ? a.w : 0.1f*a.w;
            ob[(4*j+0)*HW + p1] = b.x > 0.f ? b.x : 0.1f*b.x;
            ob[(4*j+1)*HW + p1] = b.y > 0.f ? b.y : 0.1f*b.y;
            ob[(4*j+2)*HW + p1] = b.z > 0.f ? b.z : 0.1f*b.z;
            ob[(4*j+3)*HW + p1] = b.w > 0.f ? b.w : 0.1f*b.w;
        }
    } else {
        size_t base = (size_t)(n*T + t) * C * HW + (size_t)(ocg*16)*HW;
        const float* res = feats + base;
        float*       ob  = outp  + base;
        #pragma unroll
        for (int j = 0; j < 4; j++) {
            float4 a = acc0[j], b = acc1[j];
            ob[(4*j+0)*HW + p0] = a.x + res[(4*j+0)*HW + p0];
            ob[(4*j+1)*HW + p0] = a.y + res[(4*j+1)*HW + p0];
            ob[(4*j+2)*HW + p0] = a.z + res[(4*j+2)*HW + p0];
            ob[(4*j+3)*HW + p0] = a.w + res[(4*j+3)*HW + p0];
            ob[(4*j+0)*HW + p1] = b.x + res[(4*j+0)*HW + p1];
            ob[(4*j+1)*HW + p1] = b.y + res[(4*j+1)*HW + p1];
            ob[(4*j+2)*HW + p1] = b.z + res[(4*j+2)*HW + p1];
            ob[(4*j+3)*HW + p1] = b.w + res[(4*j+3)*HW + p1];
        }
    }
}

// ---------------- launch ----------------
extern "C" void kernel_launch(void* const* d_in, const int* in_sizes, int n_in,
                              void* d_out, int out_size) {
    const float* feats = (const float*)d_in[0];
    const float* flows = (const float*)d_in[1];
    const float* bfc   = (const float*)d_in[3];
    const float* b1    = (const float*)d_in[5];
    const float* b2    = (const float*)d_in[7];
    float* out = (float*)d_out;
    (void)in_sizes; (void)n_in; (void)out_size;

    k_prep<<<(C*9*C + 255)/256, 256>>>((const float*)d_in[2],
                                       (const float*)d_in[4],
                                       (const float*)d_in[6]);

    dim3 wgrid(NB*H, 4);
    dim3 fgrid(NB*64, 4);
    dim3 cgrid(8, 8, NB*4);
    for (int t = 0; t < T; t++) {
        k_warp<<<wgrid, 128>>>(feats, flows, out, t);
        k_fc<<<fgrid, 128>>>(feats, bfc, t);
        k_conv3<<<cgrid, 128>>>(out, b1, feats, 0, t);
        k_conv3<<<cgrid, 128>>>(out, b2, feats, 1, t);
    }
}

// round 5
// speedup vs baseline: 1.7753x; 1.0796x over previous
#include <cuda_runtime.h>

#define NB 2
#define T  16
#define C  64
#define H  128
#define W  128
#define HW (H*W)

#define CH2 16   // ci chunk held in smem (conv3)

// ---------------- scratch (no allocation allowed) ----------------
__device__ float g_comb[NB*2*C*HW];     // [n][a2:0-63 | a1:64-127][HW]
__device__ float g_infeat[NB*C*HW];     // 1x1-conv output per step
__device__ float g_h1[NB*C*HW];         // conv1+leaky output per step
__device__ float g_wfc_t[3*C*C];        // [192][64]  (c-major, oc contiguous)
__device__ float g_w1_t[C*9*C];         // [(ci*9+k)][64]
__device__ float g_w2_t[C*9*C];

// ---------------- weight transposition ----------------
__global__ void k_prep(const float* __restrict__ Wfc,
                       const float* __restrict__ W1,
                       const float* __restrict__ W2) {
    int i = blockIdx.x * blockDim.x + threadIdx.x;
    if (i < 3*C*C) {                      // 12288
        int c = i >> 6, oc = i & 63;      // Wfc layout: [oc][3C]
        g_wfc_t[i] = Wfc[oc * (3*C) + c];
    }
    if (i < C*9*C) {                      // 36864
        int ck = i >> 6, oc = i & 63;
        int ci = ck / 9, k = ck % 9;      // W layout: [oc][ci][3][3]
        g_w1_t[i] = W1[(oc*C + ci)*9 + k];
        g_w2_t[i] = W2[(oc*C + ci)*9 + k];
    }
}

// ---------------- bilinear sampling helpers ----------------
struct Samp { int o00, o01, o10, o11; float w00, w01, w10, w11; };

__device__ __forceinline__ Samp make_samp(float gx, float gy) {
    float x0f = floorf(gx), y0f = floorf(gy);
    float wx = gx - x0f, wy = gy - y0f;
    int x0 = (int)x0f, y0 = (int)y0f;
    int x1 = x0 + 1,  y1 = y0 + 1;
    bool vx0 = (x0 >= 0) && (x0 < W), vx1 = (x1 >= 0) && (x1 < W);
    bool vy0 = (y0 >= 0) && (y0 < H), vy1 = (y1 >= 0) && (y1 < H);
    int cx0 = min(max(x0, 0), W-1), cx1 = min(max(x1, 0), W-1);
    int cy0 = min(max(y0, 0), H-1), cy1 = min(max(y1, 0), H-1);
    Samp s;
    s.o00 = cy0*W + cx0; s.o01 = cy0*W + cx1;
    s.o10 = cy1*W + cx0; s.o11 = cy1*W + cx1;
    s.w00 = (vx0 && vy0) ? (1.f-wx)*(1.f-wy) : 0.f;
    s.w01 = (vx1 && vy0) ? wx*(1.f-wy)       : 0.f;
    s.w10 = (vx0 && vy1) ? (1.f-wx)*wy       : 0.f;
    s.w11 = (vx1 && vy1) ? wx*wy             : 0.f;
    return s;
}

__device__ __forceinline__ float bsample(const float* __restrict__ p, const Samp& s) {
    return p[s.o00]*s.w00 + p[s.o01]*s.w01 + p[s.o10]*s.w10 + p[s.o11]*s.w11;
}

// ---------------- kernel 1a: flow warps -> g_comb ----------------
// grid (NB*H, 4 ci-groups), block 128
__global__ __launch_bounds__(128) void k_warp(
    const float* __restrict__ feats, const float* __restrict__ flows,
    const float* __restrict__ out, int t)
{
    int bx = blockIdx.x;
    int n = bx >> 7, y = bx & 127, x = threadIdx.x;
    int cig = blockIdx.y;                 // 16 channels per group
    int pix = y * W + x;

    const float* y1p = (t >= 1) ? out   + (size_t)(n*T + (t-1)) * C * HW
                                : feats + (size_t)(n*T)         * C * HW;
    const float* y2p = (t >= 2) ? out   + (size_t)(n*T + (t-2)) * C * HW
                                : feats + (size_t)(n*T)         * C * HW;

    float f1x = 0.f, f1y = 0.f;
    if (t >= 1) {
        const float* f1p = flows + (size_t)(n*T + (t-1)) * 2 * HW;
        f1x = f1p[pix]; f1y = f1p[HW + pix];
    }
    Samp s1 = make_samp((float)x + f1x, (float)y + f1y);

    float f2cx = f1x, f2cy = f1y;         // t<2: f2=0 -> warp(f2)=0 -> f2c=f1
    if (t >= 2) {
        const float* f2p = flows + (size_t)(n*T + (t-2)) * 2 * HW;
        f2cx += bsample(f2p,      s1);
        f2cy += bsample(f2p + HW, s1);
    }
    Samp s2 = make_samp((float)x + f2cx, (float)y + f2cy);

    float* a2o = g_comb + (size_t)n * 2*C*HW + pix;          // ch 0..63
    float* a1o = a2o + (size_t)C*HW;                         // ch 64..127

    int c0 = cig * 16;
    #pragma unroll 4
    for (int ci = c0; ci < c0 + 16; ci++) {
        a2o[ci*HW] = bsample(y2p + ci*HW, s2);
        a1o[ci*HW] = bsample(y1p + ci*HW, s1);
    }
}

// ---------------- kernel 1b: 1x1 conv 192->64, 2 pixels/thread ----------------
// grid (NB*64, 8 oc-groups), block 128; thread handles rows y and y+64, 8 oc
__global__ __launch_bounds__(128) void k_fc(
    const float* __restrict__ feats, const float* __restrict__ bfc, int t)
{
    int bx = blockIdx.x;
    int n = bx >> 6, y = bx & 63, x = threadIdx.x;
    int ocg = blockIdx.y;                 // 8 oc per group
    int pix0 = y * W + x;
    int pix1 = (y + 64) * W + x;

    const float* cb = g_comb + (size_t)n * 2*C*HW;                     // 128 ch
    const float* xb = feats + (size_t)(n*T + t) * C * HW;              // 64 ch

    float4 acc0[2], acc1[2];
    #pragma unroll
    for (int j = 0; j < 2; j++) {
        acc0[j] = __ldg((const float4*)bfc + ocg*2 + j);
        acc1[j] = acc0[j];
    }

    #pragma unroll 4
    for (int c = 0; c < 2*C; c++) {
        float v0 = cb[c*HW + pix0];
        float v1 = cb[c*HW + pix1];
        const float4* wr = (const float4*)(g_wfc_t + (size_t)c * C) + ocg*2;
        #pragma unroll
        for (int j = 0; j < 2; j++) {
            float4 w = __ldg(&wr[j]);
            acc0[j].x += v0*w.x; acc0[j].y += v0*w.y;
            acc0[j].z += v0*w.z; acc0[j].w += v0*w.w;
            acc1[j].x += v1*w.x; acc1[j].y += v1*w.y;
            acc1[j].z += v1*w.z; acc1[j].w += v1*w.w;
        }
    }
    #pragma unroll 4
    for (int c = 0; c < C; c++) {
        float v0 = xb[c*HW + pix0];
        float v1 = xb[c*HW + pix1];
        const float4* wr = (const float4*)(g_wfc_t + (size_t)(2*C + c) * C) + ocg*2;
        #pragma unroll
        for (int j = 0; j < 2; j++) {
            float4 w = __ldg(&wr[j]);
            acc0[j].x += v0*w.x; acc0[j].y += v0*w.y;
            acc0[j].z += v0*w.z; acc0[j].w += v0*w.w;
            acc1[j].x += v1*w.x; acc1[j].y += v1*w.y;
            acc1[j].z += v1*w.z; acc1[j].w += v1*w.w;
        }
    }

    float* ob = g_infeat + (size_t)n * C * HW + (size_t)(ocg*8)*HW;
    #pragma unroll
    for (int j = 0; j < 2; j++) {
        ob[(4*j+0)*HW + pix0] = acc0[j].x;
        ob[(4*j+1)*HW + pix0] = acc0[j].y;
        ob[(4*j+2)*HW + pix0] = acc0[j].z;
        ob[(4*j+3)*HW + pix0] = acc0[j].w;
        ob[(4*j+0)*HW + pix1] = acc1[j].x;
        ob[(4*j+1)*HW + pix1] = acc1[j].y;
        ob[(4*j+2)*HW + pix1] = acc1[j].z;
        ob[(4*j+3)*HW + pix1] = acc1[j].w;
    }
}

// ---------------- kernels 2/3: 3x3 conv, 64->64, SAME, zero pad ----------------
// grid (8, 8, NB*8), block 128 (16x8); thread = vertical pixel pair x 8 oc
// phase 0: g_infeat -> leaky_relu -> g_h1
// phase 1: g_h1 -> + feats[t] -> d_out[t]
__global__ __launch_bounds__(128, 8) void k_conv3(
    float* __restrict__ outp, const float* __restrict__ bias,
    const float* __restrict__ feats, int phase, int t)
{
    __shared__ float s[CH2][18][18];           // 16*18*18*4 = 20736 B
    int n   = blockIdx.z >> 3;
    int ocg = blockIdx.z & 7;                  // 8 oc per group
    int gx0 = blockIdx.x * 16 - 1;
    int gy0 = blockIdx.y * 16 - 1;
    int tid = threadIdx.x;
    int tx = tid & 15, ty = tid >> 4;          // ty: 0..7 -> rows 2ty, 2ty+1

    const float* inb = (phase ? g_h1 : g_infeat) + (size_t)n * C * HW;
    const float* wt  = phase ? g_w2_t : g_w1_t;

    float4 acc0[2], acc1[2];
    #pragma unroll
    for (int j = 0; j < 2; j++) {
        acc0[j] = __ldg((const float4*)bias + ocg*2 + j);
        acc1[j] = acc0[j];
    }

    for (int cc = 0; cc < C; cc += CH2) {
        if (cc) __syncthreads();
        for (int i = tid; i < CH2*18*18; i += 128) {
            int ci = i / (18*18);
            int r  = i % (18*18);
            int ry = r / 18, rx = r % 18;
            int gy = gy0 + ry, gx = gx0 + rx;
            float v = 0.f;
            if (gy >= 0 && gy < H && gx >= 0 && gx < W)
                v = inb[(cc+ci)*HW + gy*W + gx];
            s[ci][ry][rx] = v;
        }
        __syncthreads();

        for (int ci = 0; ci < CH2; ci++) {
            float v[4][3];                     // rows 2ty..2ty+3, cols tx..tx+2
            #pragma unroll
            for (int r = 0; r < 4; r++)
                #pragma unroll
                for (int c3 = 0; c3 < 3; c3++)
                    v[r][c3] = s[ci][2*ty + r][tx + c3];
            #pragma unroll
            for (int ky = 0; ky < 3; ky++) {
                #pragma unroll
                for (int kx = 0; kx < 3; kx++) {
                    const float4* wr =
                        (const float4*)(wt + (size_t)((cc+ci)*9 + ky*3 + kx) * C) + ocg*2;
                    float vk0 = v[ky][kx];
                    float vk1 = v[ky+1][kx];
                    #pragma unroll
                    for (int j = 0; j < 2; j++) {
                        float4 w = __ldg(&wr[j]);
                        acc0[j].x += vk0*w.x; acc0[j].y += vk0*w.y;
                        acc0[j].z += vk0*w.z; acc0[j].w += vk0*w.w;
                        acc1[j].x += vk1*w.x; acc1[j].y += vk1*w.y;
                        acc1[j].z += vk1*w.z; acc1[j].w += vk1*w.w;
                    }
                }
            }
        }
    }

    int y0 = gy0 + 1 + 2*ty, x = gx0 + 1 + tx;
    int p0 = y0 * W + x;
    int p1 = p0 + W;

    if (phase == 0) {
        float* ob = g_h1 + (size_t)n * C * HW + (size_t)(ocg*8)*HW;
        #pragma unroll
        for (int j = 0; j < 2; j++) {
            float4 a = acc0[j], b = acc1[j];
            ob[(4*j+0)*HW + p0] = a.x > 0.f ? a.x : 0.1f*a.x;
            ob[(4*j+1)*HW + p0] = a.y > 0.f ? a.y : 0.1f*a.y;
            ob[(4*j+2)*HW + p0] = a.z > 0.f ? a.z : 0.1f*a.z;
            ob[(4*j+3)*HW + p0] = a.w > 0.f ? a.w : 0.1f*a.w;
            ob[(4*j+0)*HW + p1] = b.x > 0.f ? b.x : 0.1f*b.x;
            ob[(4*j+1)*HW + p1] = b.y > 0.f ? b.y : 0.1f*b.y;
            ob[(4*j+2)*HW + p1] = b.z > 0.f ? b.z : 0.1f*b.z;
            ob[(4*j+3)*HW + p1] = b.w > 0.f ? b.w : 0.1f*b.w;
        }
    } else {
        size_t base = (size_t)(n*T + t) * C * HW + (size_t)(ocg*8)*HW;
        const float* res = feats + base;
        float*       ob  = outp  + base;
        #pragma unroll
        for (int j = 0; j < 2; j++) {
            float4 a = acc0[j], b = acc1[j];
            ob[(4*j+0)*HW + p0] = a.x + res[(4*j+0)*HW + p0];
            ob[(4*j+1)*HW + p0] = a.y + res[(4*j+1)*HW + p0];
            ob[(4*j+2)*HW + p0] = a.z + res[(4*j+2)*HW + p0];
            ob[(4*j+3)*HW + p0] = a.w + res[(4*j+3)*HW + p0];
            ob[(4*j+0)*HW + p1] = b.x + res[(4*j+0)*HW + p1];
            ob[(4*j+1)*HW + p1] = b.y + res[(4*j+1)*HW + p1];
            ob[(4*j+2)*HW + p1] = b.z + res[(4*j+2)*HW + p1];
            ob[(4*j+3)*HW + p1] = b.w + res[(4*j+3)*HW + p1];
        }
    }
}

// ---------------- launch ----------------
extern "C" void kernel_launch(void* const* d_in, const int* in_sizes, int n_in,
                              void* d_out, int out_size) {
    const float* feats = (const float*)d_in[0];
    const float* flows = (const float*)d_in[1];
    const float* bfc   = (const float*)d_in[3];
    const float* b1    = (const float*)d_in[5];
    const float* b2    = (const float*)d_in[7];
    float* out = (float*)d_out;
    (void)in_sizes; (void)n_in; (void)out_size;

    k_prep<<<(C*9*C + 255)/256, 256>>>((const float*)d_in[2],
                                       (const float*)d_in[4],
                                       (const float*)d_in[6]);

    dim3 wgrid(NB*H, 4);
    dim3 fgrid(NB*64, 8);
    dim3 cgrid(8, 8, NB*8);
    for (int t = 0; t < T; t++) {
        k_warp<<<wgrid, 128>>>(feats, flows, out, t);
        k_fc<<<fgrid, 128>>>(feats, bfc, t);
        k_conv3<<<cgrid, 128>>>(out, b1, feats, 0, t);
        k_conv3<<<cgrid, 128>>>(out, b2, feats, 1, t);
    }
}

// round 6
// speedup vs baseline: 2.0361x; 1.1469x over previous
#include <cuda_runtime.h>

#define NB 2
#define T  16
#define C  64
#define H  128
#define W  128
#define HW (H*W)

#define CH2 16    // ci chunk held in smem (conv3)
#define SROW 24   // padded smem row stride (bank-conflict-free for row pairs)

// ---------------- scratch (no allocation allowed) ----------------
__device__ float g_comb[NB*2*C*HW];     // [n][a2:0-63 | a1:64-127][HW]
__device__ float g_infeat[NB*C*HW];     // 1x1-conv output per step
__device__ float g_h1[NB*C*HW];         // conv1+leaky output per step
__device__ float g_wfc_t[3*C*C];        // [192][64]  (c-major, oc contiguous)
__device__ float g_w1_t[C*9*C];         // [(ci*9+k)][64]
__device__ float g_w2_t[C*9*C];

// ---------------- weight transposition ----------------
__global__ void k_prep(const float* __restrict__ Wfc,
                       const float* __restrict__ W1,
                       const float* __restrict__ W2) {
    int i = blockIdx.x * blockDim.x + threadIdx.x;
    if (i < 3*C*C) {                      // 12288
        int c = i >> 6, oc = i & 63;      // Wfc layout: [oc][3C]
        g_wfc_t[i] = Wfc[oc * (3*C) + c];
    }
    if (i < C*9*C) {                      // 36864
        int ck = i >> 6, oc = i & 63;
        int ci = ck / 9, k = ck % 9;      // W layout: [oc][ci][3][3]
        g_w1_t[i] = W1[(oc*C + ci)*9 + k];
        g_w2_t[i] = W2[(oc*C + ci)*9 + k];
    }
}

// ---------------- bilinear sampling helpers ----------------
struct Samp { int o00, o01, o10, o11; float w00, w01, w10, w11; };

__device__ __forceinline__ Samp make_samp(float gx, float gy) {
    float x0f = floorf(gx), y0f = floorf(gy);
    float wx = gx - x0f, wy = gy - y0f;
    int x0 = (int)x0f, y0 = (int)y0f;
    int x1 = x0 + 1,  y1 = y0 + 1;
    bool vx0 = (x0 >= 0) && (x0 < W), vx1 = (x1 >= 0) && (x1 < W);
    bool vy0 = (y0 >= 0) && (y0 < H), vy1 = (y1 >= 0) && (y1 < H);
    int cx0 = min(max(x0, 0), W-1), cx1 = min(max(x1, 0), W-1);
    int cy0 = min(max(y0, 0), H-1), cy1 = min(max(y1, 0), H-1);
    Samp s;
    s.o00 = cy0*W + cx0; s.o01 = cy0*W + cx1;
    s.o10 = cy1*W + cx0; s.o11 = cy1*W + cx1;
    s.w00 = (vx0 && vy0) ? (1.f-wx)*(1.f-wy) : 0.f;
    s.w01 = (vx1 && vy0) ? wx*(1.f-wy)       : 0.f;
    s.w10 = (vx0 && vy1) ? (1.f-wx)*wy       : 0.f;
    s.w11 = (vx1 && vy1) ? wx*wy             : 0.f;
    return s;
}

__device__ __forceinline__ float bsample(const float* __restrict__ p, const Samp& s) {
    return p[s.o00]*s.w00 + p[s.o01]*s.w01 + p[s.o10]*s.w10 + p[s.o11]*s.w11;
}

// ---------------- kernel 1a: flow warps -> g_comb ----------------
// grid (NB*H, 4 ci-groups), block 128
__global__ __launch_bounds__(128) void k_warp(
    const float* __restrict__ feats, const float* __restrict__ flows,
    const float* __restrict__ out, int t)
{
    int bx = blockIdx.x;
    int n = bx >> 7, y = bx & 127, x = threadIdx.x;
    int cig = blockIdx.y;                 // 16 channels per group
    int pix = y * W + x;

    const float* y1p = (t >= 1) ? out   + (size_t)(n*T + (t-1)) * C * HW
                                : feats + (size_t)(n*T)         * C * HW;
    const float* y2p = (t >= 2) ? out   + (size_t)(n*T + (t-2)) * C * HW
                                : feats + (size_t)(n*T)         * C * HW;

    float f1x = 0.f, f1y = 0.f;
    if (t >= 1) {
        const float* f1p = flows + (size_t)(n*T + (t-1)) * 2 * HW;
        f1x = f1p[pix]; f1y = f1p[HW + pix];
    }
    Samp s1 = make_samp((float)x + f1x, (float)y + f1y);

    float f2cx = f1x, f2cy = f1y;         // t<2: f2=0 -> warp(f2)=0 -> f2c=f1
    if (t >= 2) {
        const float* f2p = flows + (size_t)(n*T + (t-2)) * 2 * HW;
        f2cx += bsample(f2p,      s1);
        f2cy += bsample(f2p + HW, s1);
    }
    Samp s2 = make_samp((float)x + f2cx, (float)y + f2cy);

    float* a2o = g_comb + (size_t)n * 2*C*HW + pix;          // ch 0..63
    float* a1o = a2o + (size_t)C*HW;                         // ch 64..127

    int c0 = cig * 16;
    #pragma unroll 4
    for (int ci = c0; ci < c0 + 16; ci++) {
        a2o[ci*HW] = bsample(y2p + ci*HW, s2);
        a1o[ci*HW] = bsample(y1p + ci*HW, s1);
    }
}

// ---------------- kernel 1b: 1x1 conv 192->64, 2 pixels/thread ----------------
// grid (NB*64, 8 oc-groups), block 128; thread handles rows y and y+64, 8 oc
__global__ __launch_bounds__(128) void k_fc(
    const float* __restrict__ feats, const float* __restrict__ bfc, int t)
{
    int bx = blockIdx.x;
    int n = bx >> 6, y = bx & 63, x = threadIdx.x;
    int ocg = blockIdx.y;                 // 8 oc per group
    int pix0 = y * W + x;
    int pix1 = (y + 64) * W + x;

    const float* cb = g_comb + (size_t)n * 2*C*HW;                     // 128 ch
    const float* xb = feats + (size_t)(n*T + t) * C * HW;              // 64 ch

    float4 acc0[2], acc1[2];
    #pragma unroll
    for (int j = 0; j < 2; j++) {
        acc0[j] = __ldg((const float4*)bfc + ocg*2 + j);
        acc1[j] = acc0[j];
    }

    #pragma unroll 4
    for (int c = 0; c < 2*C; c++) {
        float v0 = cb[c*HW + pix0];
        float v1 = cb[c*HW + pix1];
        const float4* wr = (const float4*)(g_wfc_t + (size_t)c * C) + ocg*2;
        #pragma unroll
        for (int j = 0; j < 2; j++) {
            float4 w = __ldg(&wr[j]);
            acc0[j].x += v0*w.x; acc0[j].y += v0*w.y;
            acc0[j].z += v0*w.z; acc0[j].w += v0*w.w;
            acc1[j].x += v1*w.x; acc1[j].y += v1*w.y;
            acc1[j].z += v1*w.z; acc1[j].w += v1*w.w;
        }
    }
    #pragma unroll 4
    for (int c = 0; c < C; c++) {
        float v0 = xb[c*HW + pix0];
        float v1 = xb[c*HW + pix1];
        const float4* wr = (const float4*)(g_wfc_t + (size_t)(2*C + c) * C) + ocg*2;
        #pragma unroll
        for (int j = 0; j < 2; j++) {
            float4 w = __ldg(&wr[j]);
            acc0[j].x += v0*w.x; acc0[j].y += v0*w.y;
            acc0[j].z += v0*w.z; acc0[j].w += v0*w.w;
            acc1[j].x += v1*w.x; acc1[j].y += v1*w.y;
            acc1[j].z += v1*w.z; acc1[j].w += v1*w.w;
        }
    }

    float* ob = g_infeat + (size_t)n * C * HW + (size_t)(ocg*8)*HW;
    #pragma unroll
    for (int j = 0; j < 2; j++) {
        ob[(4*j+0)*HW + pix0] = acc0[j].x;
        ob[(4*j+1)*HW + pix0] = acc0[j].y;
        ob[(4*j+2)*HW + pix0] = acc0[j].z;
        ob[(4*j+3)*HW + pix0] = acc0[j].w;
        ob[(4*j+0)*HW + pix1] = acc1[j].x;
        ob[(4*j+1)*HW + pix1] = acc1[j].y;
        ob[(4*j+2)*HW + pix1] = acc1[j].z;
        ob[(4*j+3)*HW + pix1] = acc1[j].w;
    }
}

// ---------------- kernels 2/3: 3x3 conv, 64->64, SAME, zero pad ----------------
// grid (8, 8, NB*8), block 128 (16x8); thread = vertical pixel pair x 8 oc
// phase 0: g_infeat -> leaky_relu -> g_h1
// phase 1: g_h1 -> + feats[t] -> d_out[t]
__global__ __launch_bounds__(128, 8) void k_conv3(
    float* __restrict__ outp, const float* __restrict__ bias,
    const float* __restrict__ feats, int phase, int t)
{
    __shared__ float s[CH2][18][SROW];         // 16*18*24*4 = 27648 B
    int n   = blockIdx.z >> 3;
    int ocg = blockIdx.z & 7;                  // 8 oc per group
    int gx0 = blockIdx.x * 16 - 1;
    int gy0 = blockIdx.y * 16 - 1;
    int tid = threadIdx.x;
    int tx = tid & 15, ty = tid >> 4;          // ty: 0..7 -> rows 2ty, 2ty+1

    const float* inb = (phase ? g_h1 : g_infeat) + (size_t)n * C * HW;
    const float* wt  = phase ? g_w2_t : g_w1_t;

    // ---- precompute fill positions (once; no div/mod in hot loop) ----
    bool fin[3], fvd[3];
    int  gof[3], sof[3];
    #pragma unroll
    for (int q = 0; q < 3; q++) {
        int p = tid + q*128;
        bool inr = (p < 18*18);
        int ry = p / 18, rx = p - ry*18;
        int gy = gy0 + ry, gx = gx0 + rx;
        fin[q] = inr;
        fvd[q] = inr && (gy >= 0) && (gy < H) && (gx >= 0) && (gx < W);
        gof[q] = gy*W + gx;
        sof[q] = ry*SROW + rx;
    }
    float* sp = &s[0][0][0];

    float4 acc0[2], acc1[2];
    #pragma unroll
    for (int j = 0; j < 2; j++) {
        acc0[j] = __ldg((const float4*)bias + ocg*2 + j);
        acc1[j] = acc0[j];
    }

    for (int cc = 0; cc < C; cc += CH2) {
        if (cc) __syncthreads();
        #pragma unroll
        for (int q = 0; q < 3; q++) {
            if (fin[q]) {
                const float* gb = inb + (size_t)cc*HW + gof[q];
                float* sb = sp + sof[q];
                #pragma unroll
                for (int ci = 0; ci < CH2; ci++) {
                    float v = fvd[q] ? gb[ci*HW] : 0.f;
                    sb[ci*(18*SROW)] = v;
                }
            }
        }
        __syncthreads();

        #pragma unroll 4
        for (int ci = 0; ci < CH2; ci++) {
            float v[4][3];                     // rows 2ty..2ty+3, cols tx..tx+2
            #pragma unroll
            for (int r = 0; r < 4; r++)
                #pragma unroll
                for (int c3 = 0; c3 < 3; c3++)
                    v[r][c3] = s[ci][2*ty + r][tx + c3];
            #pragma unroll
            for (int ky = 0; ky < 3; ky++) {
                #pragma unroll
                for (int kx = 0; kx < 3; kx++) {
                    const float4* wr =
                        (const float4*)(wt + (size_t)((cc+ci)*9 + ky*3 + kx) * C) + ocg*2;
                    float vk0 = v[ky][kx];
                    float vk1 = v[ky+1][kx];
                    #pragma unroll
                    for (int j = 0; j < 2; j++) {
                        float4 w = __ldg(&wr[j]);
                        acc0[j].x += vk0*w.x; acc0[j].y += vk0*w.y;
                        acc0[j].z += vk0*w.z; acc0[j].w += vk0*w.w;
                        acc1[j].x += vk1*w.x; acc1[j].y += vk1*w.y;
                        acc1[j].z += vk1*w.z; acc1[j].w += vk1*w.w;
                    }
                }
            }
        }
    }

    int y0 = gy0 + 1 + 2*ty, x = gx0 + 1 + tx;
    int p0 = y0 * W + x;
    int p1 = p0 + W;

    if (phase == 0) {
        float* ob = g_h1 + (size_t)n * C * HW + (size_t)(ocg*8)*HW;
        #pragma unroll
        for (int j = 0; j < 2; j++) {
            float4 a = acc0[j], b = acc1[j];
            ob[(4*j+0)*HW + p0] = a.x > 0.f ? a.x : 0.1f*a.x;
            ob[(4*j+1)*HW + p0] = a.y > 0.f ? a.y : 0.1f*a.y;
            ob[(4*j+2)*HW + p0] = a.z > 0.f ? a.z : 0.1f*a.z;
            ob[(4*j+3)*HW + p0] = a.w > 0.f ? a.w : 0.1f*a.w;
            ob[(4*j+0)*HW + p1] = b.x > 0.f ? b.x : 0.1f*b.x;
            ob[(4*j+1)*HW + p1] = b.y > 0.f ? b.y : 0.1f*b.y;
            ob[(4*j+2)*HW + p1] = b.z > 0.f ? b.z : 0.1f*b.z;
            ob[(4*j+3)*HW + p1] = b.w > 0.f ? b.w : 0.1f*b.w;
        }
    } else {
        size_t base = (size_t)(n*T + t) * C * HW + (size_t)(ocg*8)*HW;
        const float* res = feats + base;
        float*       ob  = outp  + base;
        #pragma unroll
        for (int j = 0; j < 2; j++) {
            float4 a = acc0[j], b = acc1[j];
            ob[(4*j+0)*HW + p0] = a.x + res[(4*j+0)*HW + p0];
            ob[(4*j+1)*HW + p0] = a.y + res[(4*j+1)*HW + p0];
            ob[(4*j+2)*HW + p0] = a.z + res[(4*j+2)*HW + p0];
            ob[(4*j+3)*HW + p0] = a.w + res[(4*j+3)*HW + p0];
            ob[(4*j+0)*HW + p1] = b.x + res[(4*j+0)*HW + p1];
            ob[(4*j+1)*HW + p1] = b.y + res[(4*j+1)*HW + p1];
            ob[(4*j+2)*HW + p1] = b.z + res[(4*j+2)*HW + p1];
            ob[(4*j+3)*HW + p1] = b.w + res[(4*j+3)*HW + p1];
        }
    }
}

// ---------------- launch ----------------
extern "C" void kernel_launch(void* const* d_in, const int* in_sizes, int n_in,
                              void* d_out, int out_size) {
    const float* feats = (const float*)d_in[0];
    const float* flows = (const float*)d_in[1];
    const float* bfc   = (const float*)d_in[3];
    const float* b1    = (const float*)d_in[5];
    const float* b2    = (const float*)d_in[7];
    float* out = (float*)d_out;
    (void)in_sizes; (void)n_in; (void)out_size;

    k_prep<<<(C*9*C + 255)/256, 256>>>((const float*)d_in[2],
                                       (const float*)d_in[4],
                                       (const float*)d_in[6]);

    dim3 wgrid(NB*H, 4);
    dim3 fgrid(NB*64, 8);
    dim3 cgrid(8, 8, NB*8);
    for (int t = 0; t < T; t++) {
        k_warp<<<wgrid, 128>>>(feats, flows, out, t);
        k_fc<<<fgrid, 128>>>(feats, bfc, t);
        k_conv3<<<cgrid, 128>>>(out, b1, feats, 0, t);
        k_conv3<<<cgrid, 128>>>(out, b2, feats, 1, t);
    }
}

// round 7
// speedup vs baseline: 2.3275x; 1.1431x over previous
#include <cuda_runtime.h>

#define NB 2
#define T  16
#define C  64
#define H  128
#define W  128
#define HW (H*W)

#define CH3 8     // ci chunk held in smem (conv3)
#define SR3 36    // smem row stride in floats (34 used, float4-aligned)

// ---------------- scratch (no allocation allowed) ----------------
__device__ float g_comb[NB*2*C*HW];     // [n][a2:0-63 | a1:64-127][HW]
__device__ float g_infeat[NB*C*HW];     // 1x1-conv output per step
__device__ float g_h1[NB*C*HW];         // conv1+leaky output per step
__device__ float g_wfc_t[3*C*C];        // [192][64]  (c-major, oc contiguous)
__device__ float g_w1_t[C*9*C];         // [(ci*9+k)][64]
__device__ float g_w2_t[C*9*C];

// ---------------- weight transposition ----------------
__global__ void k_prep(const float* __restrict__ Wfc,
                       const float* __restrict__ W1,
                       const float* __restrict__ W2) {
    int i = blockIdx.x * blockDim.x + threadIdx.x;
    if (i < 3*C*C) {                      // 12288
        int c = i >> 6, oc = i & 63;      // Wfc layout: [oc][3C]
        g_wfc_t[i] = Wfc[oc * (3*C) + c];
    }
    if (i < C*9*C) {                      // 36864
        int ck = i >> 6, oc = i & 63;
        int ci = ck / 9, k = ck % 9;      // W layout: [oc][ci][3][3]
        g_w1_t[i] = W1[(oc*C + ci)*9 + k];
        g_w2_t[i] = W2[(oc*C + ci)*9 + k];
    }
}

// ---------------- bilinear sampling helpers ----------------
struct Samp { int o00, o01, o10, o11; float w00, w01, w10, w11; };

__device__ __forceinline__ Samp make_samp(float gx, float gy) {
    float x0f = floorf(gx), y0f = floorf(gy);
    float wx = gx - x0f, wy = gy - y0f;
    int x0 = (int)x0f, y0 = (int)y0f;
    int x1 = x0 + 1,  y1 = y0 + 1;
    bool vx0 = (x0 >= 0) && (x0 < W), vx1 = (x1 >= 0) && (x1 < W);
    bool vy0 = (y0 >= 0) && (y0 < H), vy1 = (y1 >= 0) && (y1 < H);
    int cx0 = min(max(x0, 0), W-1), cx1 = min(max(x1, 0), W-1);
    int cy0 = min(max(y0, 0), H-1), cy1 = min(max(y1, 0), H-1);
    Samp s;
    s.o00 = cy0*W + cx0; s.o01 = cy0*W + cx1;
    s.o10 = cy1*W + cx0; s.o11 = cy1*W + cx1;
    s.w00 = (vx0 && vy0) ? (1.f-wx)*(1.f-wy) : 0.f;
    s.w01 = (vx1 && vy0) ? wx*(1.f-wy)       : 0.f;
    s.w10 = (vx0 && vy1) ? (1.f-wx)*wy       : 0.f;
    s.w11 = (vx1 && vy1) ? wx*wy             : 0.f;
    return s;
}

__device__ __forceinline__ float bsample(const float* __restrict__ p, const Samp& s) {
    return p[s.o00]*s.w00 + p[s.o01]*s.w01 + p[s.o10]*s.w10 + p[s.o11]*s.w11;
}

// ---------------- kernel 1a: flow warps -> g_comb ----------------
// grid (NB*H, 4 ci-groups), block 128
__global__ __launch_bounds__(128) void k_warp(
    const float* __restrict__ feats, const float* __restrict__ flows,
    const float* __restrict__ out, int t)
{
    int bx = blockIdx.x;
    int n = bx >> 7, y = bx & 127, x = threadIdx.x;
    int cig = blockIdx.y;                 // 16 channels per group
    int pix = y * W + x;

    const float* y1p = (t >= 1) ? out   + (size_t)(n*T + (t-1)) * C * HW
                                : feats + (size_t)(n*T)         * C * HW;
    const float* y2p = (t >= 2) ? out   + (size_t)(n*T + (t-2)) * C * HW
                                : feats + (size_t)(n*T)         * C * HW;

    float f1x = 0.f, f1y = 0.f;
    if (t >= 1) {
        const float* f1p = flows + (size_t)(n*T + (t-1)) * 2 * HW;
        f1x = f1p[pix]; f1y = f1p[HW + pix];
    }
    Samp s1 = make_samp((float)x + f1x, (float)y + f1y);

    float f2cx = f1x, f2cy = f1y;         // t<2: f2=0 -> warp(f2)=0 -> f2c=f1
    if (t >= 2) {
        const float* f2p = flows + (size_t)(n*T + (t-2)) * 2 * HW;
        f2cx += bsample(f2p,      s1);
        f2cy += bsample(f2p + HW, s1);
    }
    Samp s2 = make_samp((float)x + f2cx, (float)y + f2cy);

    float* a2o = g_comb + (size_t)n * 2*C*HW + pix;          // ch 0..63
    float* a1o = a2o + (size_t)C*HW;                         // ch 64..127

    int c0 = cig * 16;
    #pragma unroll 4
    for (int ci = c0; ci < c0 + 16; ci++) {
        a2o[ci*HW] = bsample(y2p + ci*HW, s2);
        a1o[ci*HW] = bsample(y1p + ci*HW, s1);
    }
}

// ---------------- kernel 1b: 1x1 conv 192->64 ----------------
// grid (NB*16, 16 oc-groups), block 128
// thread: 4 consecutive cols (float4) x 2 rows (y, y+64) x 4 oc
__global__ __launch_bounds__(128) void k_fc(
    const float* __restrict__ feats, const float* __restrict__ bfc, int t)
{
    int gx = blockIdx.x;
    int n = gx >> 4, yg = gx & 15;
    int ocg = blockIdx.y;                 // 4 oc per group
    int tx = threadIdx.x & 31;            // cols 4tx..4tx+3
    int ty = threadIdx.x >> 5;            // 0..3
    int y = yg*4 + ty;                    // 0..63
    int pix0 = y * W + 4*tx;
    int pix1 = (y + 64) * W + 4*tx;

    const float* cb = g_comb + (size_t)n * 2*C*HW;                     // 128 ch
    const float* xb = feats + (size_t)(n*T + t) * C * HW;              // 64 ch

    float4 acc0[4], acc1[4];               // [oc] over 4 cols
    #pragma unroll
    for (int o = 0; o < 4; o++) {
        float b = __ldg(bfc + ocg*4 + o);
        acc0[o] = make_float4(b, b, b, b);
        acc1[o] = acc0[o];
    }

    #pragma unroll 4
    for (int c = 0; c < 2*C; c++) {
        float4 v0 = __ldg((const float4*)(cb + (size_t)c*HW) + (pix0 >> 2));
        float4 v1 = __ldg((const float4*)(cb + (size_t)c*HW) + (pix1 >> 2));
        float4 wv = __ldg((const float4*)(g_wfc_t + (size_t)c * C) + ocg);
        float wo[4] = {wv.x, wv.y, wv.z, wv.w};
        #pragma unroll
        for (int o = 0; o < 4; o++) {
            acc0[o].x += v0.x*wo[o]; acc0[o].y += v0.y*wo[o];
            acc0[o].z += v0.z*wo[o]; acc0[o].w += v0.w*wo[o];
            acc1[o].x += v1.x*wo[o]; acc1[o].y += v1.y*wo[o];
            acc1[o].z += v1.z*wo[o]; acc1[o].w += v1.w*wo[o];
        }
    }
    #pragma unroll 4
    for (int c = 0; c < C; c++) {
        float4 v0 = __ldg((const float4*)(xb + (size_t)c*HW) + (pix0 >> 2));
        float4 v1 = __ldg((const float4*)(xb + (size_t)c*HW) + (pix1 >> 2));
        float4 wv = __ldg((const float4*)(g_wfc_t + (size_t)(2*C + c) * C) + ocg);
        float wo[4] = {wv.x, wv.y, wv.z, wv.w};
        #pragma unroll
        for (int o = 0; o < 4; o++) {
            acc0[o].x += v0.x*wo[o]; acc0[o].y += v0.y*wo[o];
            acc0[o].z += v0.z*wo[o]; acc0[o].w += v0.w*wo[o];
            acc1[o].x += v1.x*wo[o]; acc1[o].y += v1.y*wo[o];
            acc1[o].z += v1.z*wo[o]; acc1[o].w += v1.w*wo[o];
        }
    }

    float* ob = g_infeat + (size_t)n * C * HW;
    #pragma unroll
    for (int o = 0; o < 4; o++) {
        *((float4*)(ob + (size_t)(ocg*4+o)*HW + pix0)) = acc0[o];
        *((float4*)(ob + (size_t)(ocg*4+o)*HW + pix1)) = acc1[o];
    }
}

// ---------------- kernels 2/3: 3x3 conv, 64->64, SAME, zero pad ----------------
// grid (4, 4, NB*16), block 128; tile 32x32
// thread: 4 consecutive cols x 2 rows x 4 oc; taps via LDS.128
// phase 0: g_infeat -> leaky_relu -> g_h1
// phase 1: g_h1 -> + feats[t] -> d_out[t]
__global__ __launch_bounds__(128, 4) void k_conv3(
    float* __restrict__ outp, const float* __restrict__ bias,
    const float* __restrict__ feats, int phase, int t)
{
    __shared__ float s[CH3][34][SR3];          // 8*34*36*4 = 39168 B
    int n   = blockIdx.z >> 4;
    int ocg = blockIdx.z & 15;                 // 4 oc per group
    int gx0 = blockIdx.x * 32 - 1;             // halo origin
    int gy0 = blockIdx.y * 32 - 1;
    int tid = threadIdx.x;
    int tx = tid & 7;                          // col block: cols 4tx..4tx+3 (output)
    int ty = tid >> 3;                         // 0..15 -> output rows 2ty, 2ty+1

    const float* inb = (phase ? g_h1 : g_infeat) + (size_t)n * C * HW;
    const float* wt  = phase ? g_w2_t : g_w1_t;

    float4 acc[2][4];                          // [row][oc], lanes = 4 cols
    #pragma unroll
    for (int o = 0; o < 4; o++) {
        float b = __ldg(bias + ocg*4 + o);
        acc[0][o] = make_float4(b, b, b, b);
        acc[1][o] = acc[0][o];
    }

    for (int cc = 0; cc < C; cc += CH3) {
        if (cc) __syncthreads();
        // fill 34x34 halo tile for CH3 channels
        for (int p = tid; p < 34*34; p += 128) {
            int ry = p / 34, rx = p - ry*34;
            int gy = gy0 + ry, gx = gx0 + rx;
            bool vd = (gy >= 0) && (gy < H) && (gx >= 0) && (gx < W);
            const float* gb = inb + (size_t)cc*HW + gy*W + gx;
            float* sb = &s[0][ry][rx];
            #pragma unroll
            for (int ci = 0; ci < CH3; ci++)
                sb[ci*(34*SR3)] = vd ? gb[ci*HW] : 0.f;
        }
        __syncthreads();

        for (int ci = 0; ci < CH3; ci++) {
            // taps: 4 rows x 8 cols, via 2 LDS.128 per row
            float ta[4][8];
            const float4* s4 = (const float4*)&s[ci][0][0];   // row stride = 9 float4
            #pragma unroll
            for (int r = 0; r < 4; r++) {
                float4 a = s4[(2*ty + r)*9 + tx];
                float4 b = s4[(2*ty + r)*9 + tx + 1];
                ta[r][0]=a.x; ta[r][1]=a.y; ta[r][2]=a.z; ta[r][3]=a.w;
                ta[r][4]=b.x; ta[r][5]=b.y; ta[r][6]=b.z; ta[r][7]=b.w;
            }
            #pragma unroll
            for (int ky = 0; ky < 3; ky++) {
                #pragma unroll
                for (int kx = 0; kx < 3; kx++) {
                    float4 wv = __ldg((const float4*)(wt + (size_t)((cc+ci)*9 + ky*3 + kx) * C) + ocg);
                    float wo[4] = {wv.x, wv.y, wv.z, wv.w};
                    #pragma unroll
                    for (int pr = 0; pr < 2; pr++) {
                        #pragma unroll
                        for (int o = 0; o < 4; o++) {
                            acc[pr][o].x += ta[pr+ky][kx+0]*wo[o];
                            acc[pr][o].y += ta[pr+ky][kx+1]*wo[o];
                            acc[pr][o].z += ta[pr+ky][kx+2]*wo[o];
                            acc[pr][o].w += ta[pr+ky][kx+3]*wo[o];
                        }
                    }
                }
            }
        }
    }

    int xo = blockIdx.x*32 + 4*tx;
    int yo = blockIdx.y*32 + 2*ty;
    int p0 = yo * W + xo;
    int p1 = p0 + W;

    if (phase == 0) {
        float* ob = g_h1 + (size_t)n * C * HW;
        #pragma unroll
        for (int o = 0; o < 4; o++) {
            float4 a = acc[0][o], b = acc[1][o];
            a.x = a.x > 0.f ? a.x : 0.1f*a.x;  a.y = a.y > 0.f ? a.y : 0.1f*a.y;
            a.z = a.z > 0.f ? a.z : 0.1f*a.z;  a.w = a.w > 0.f ? a.w : 0.1f*a.w;
            b.x = b.x > 0.f ? b.x : 0.1f*b.x;  b.y = b.y > 0.f ? b.y : 0.1f*b.y;
            b.z = b.z > 0.f ? b.z : 0.1f*b.z;  b.w = b.w > 0.f ? b.w : 0.1f*b.w;
            *((float4*)(ob + (size_t)(ocg*4+o)*HW + p0)) = a;
            *((float4*)(ob + (size_t)(ocg*4+o)*HW + p1)) = b;
        }
    } else {
        size_t base = (size_t)(n*T + t) * C * HW;
        const float* res = feats + base;
        float*       ob  = outp  + base;
        #pragma unroll
        for (int o = 0; o < 4; o++) {
            size_t ch = (size_t)(ocg*4+o)*HW;
            float4 r0 = __ldg((const float4*)(res + ch + p0));
            float4 r1 = __ldg((const float4*)(res + ch + p1));
            float4 a = acc[0][o], b = acc[1][o];
            a.x += r0.x; a.y += r0.y; a.z += r0.z; a.w += r0.w;
            b.x += r1.x; b.y += r1.y; b.z += r1.z; b.w += r1.w;
            *((float4*)(ob + ch + p0)) = a;
            *((float4*)(ob + ch + p1)) = b;
        }
    }
}

// ---------------- launch ----------------
extern "C" void kernel_launch(void* const* d_in, const int* in_sizes, int n_in,
                              void* d_out, int out_size) {
    const float* feats = (const float*)d_in[0];
    const float* flows = (const float*)d_in[1];
    const float* bfc   = (const float*)d_in[3];
    const float* b1    = (const float*)d_in[5];
    const float* b2    = (const float*)d_in[7];
    float* out = (float*)d_out;
    (void)in_sizes; (void)n_in; (void)out_size;

    k_prep<<<(C*9*C + 255)/256, 256>>>((const float*)d_in[2],
                                       (const float*)d_in[4],
                                       (const float*)d_in[6]);

    dim3 wgrid(NB*H, 4);
    dim3 fgrid(NB*16, 16);
    dim3 cgrid(4, 4, NB*16);
    for (int t = 0; t < T; t++) {
        k_warp<<<wgrid, 128>>>(feats, flows, out, t);
        k_fc<<<fgrid, 128>>>(feats, bfc, t);
        k_conv3<<<cgrid, 128>>>(out, b1, feats, 0, t);
        k_conv3<<<cgrid, 128>>>(out, b2, feats, 1, t);
    }
}

// round 8
// speedup vs baseline: 2.6164x; 1.1241x over previous
#include <cuda_runtime.h>

#define NB 2
#define T  16
#define C  64
#define H  128
#define W  128
#define HW (H*W)

// ---------------- scratch (no allocation allowed) ----------------
__device__ float g_infeat[NB*C*HW];     // 1x1-conv output per step
__device__ float g_h1[NB*C*HW];         // conv1+leaky output per step
__device__ float g_wfc_t[3*C*C];        // [192][64]  (c-major, oc contiguous)
__device__ float g_w1_t[C*9*C];         // [(ci*9+k)][64]
__device__ float g_w2_t[C*9*C];

// ---------------- weight transposition ----------------
__global__ void k_prep(const float* __restrict__ Wfc,
                       const float* __restrict__ W1,
                       const float* __restrict__ W2) {
    int i = blockIdx.x * blockDim.x + threadIdx.x;
    if (i < 3*C*C) {                      // 12288
        int c = i >> 6, oc = i & 63;      // Wfc layout: [oc][3C]
        g_wfc_t[i] = Wfc[oc * (3*C) + c];
    }
    if (i < C*9*C) {                      // 36864
        int ck = i >> 6, oc = i & 63;
        int ci = ck / 9, k = ck % 9;      // W layout: [oc][ci][3][3]
        g_w1_t[i] = W1[(oc*C + ci)*9 + k];
        g_w2_t[i] = W2[(oc*C + ci)*9 + k];
    }
}

// ---------------- bilinear sampling helpers ----------------
struct Samp { int o00, o01, o10, o11; float w00, w01, w10, w11; };

__device__ __forceinline__ Samp make_samp(float gx, float gy) {
    float x0f = floorf(gx), y0f = floorf(gy);
    float wx = gx - x0f, wy = gy - y0f;
    int x0 = (int)x0f, y0 = (int)y0f;
    int x1 = x0 + 1,  y1 = y0 + 1;
    bool vx0 = (x0 >= 0) && (x0 < W), vx1 = (x1 >= 0) && (x1 < W);
    bool vy0 = (y0 >= 0) && (y0 < H), vy1 = (y1 >= 0) && (y1 < H);
    int cx0 = min(max(x0, 0), W-1), cx1 = min(max(x1, 0), W-1);
    int cy0 = min(max(y0, 0), H-1), cy1 = min(max(y1, 0), H-1);
    Samp s;
    s.o00 = cy0*W + cx0; s.o01 = cy0*W + cx1;
    s.o10 = cy1*W + cx0; s.o11 = cy1*W + cx1;
    s.w00 = (vx0 && vy0) ? (1.f-wx)*(1.f-wy) : 0.f;
    s.w01 = (vx1 && vy0) ? wx*(1.f-wy)       : 0.f;
    s.w10 = (vx0 && vy1) ? (1.f-wx)*wy       : 0.f;
    s.w11 = (vx1 && vy1) ? wx*wy             : 0.f;
    return s;
}

__device__ __forceinline__ float bsample(const float* __restrict__ p, const Samp& s) {
    return p[s.o00]*s.w00 + p[s.o01]*s.w01 + p[s.o10]*s.w10 + p[s.o11]*s.w11;
}

// ---------------- kernel 1: fused flow warp + 1x1 conv (192->64) ----------------
// grid NB*256 (CTA = 64 consecutive pixels, all 64 oc), block 256
__global__ __launch_bounds__(256) void k_wfc(
    const float* __restrict__ feats, const float* __restrict__ flows,
    const float* __restrict__ out,   const float* __restrict__ bfc, int t)
{
    __shared__ float sin[2*C][64];       // a2: ch 0..63, a1: ch 64..127 (32 KB)
    __shared__ Samp ss1[64], ss2[64];    // 4 KB

    int bid = blockIdx.x;
    int n = bid >> 8, rem = bid & 255;
    int y = rem >> 1, x0 = (rem & 1) * 64;
    int tid = threadIdx.x;

    const float* y1p = (t >= 1) ? out   + (size_t)(n*T + (t-1)) * C * HW
                                : feats + (size_t)(n*T)         * C * HW;
    const float* y2p = (t >= 2) ? out   + (size_t)(n*T + (t-2)) * C * HW
                                : feats + (size_t)(n*T)         * C * HW;

    // ---- phase A0: per-pixel Samp (64 threads) ----
    if (tid < 64) {
        int x = x0 + tid;
        int pix = y * W + x;
        float f1x = 0.f, f1y = 0.f;
        if (t >= 1) {
            const float* f1p = flows + (size_t)(n*T + (t-1)) * 2 * HW;
            f1x = f1p[pix]; f1y = f1p[HW + pix];
        }
        Samp s1 = make_samp((float)x + f1x, (float)y + f1y);
        float f2cx = f1x, f2cy = f1y;    // t<2: f2=0 -> warp(f2)=0 -> f2c=f1
        if (t >= 2) {
            const float* f2p = flows + (size_t)(n*T + (t-2)) * 2 * HW;
            f2cx += bsample(f2p,      s1);
            f2cy += bsample(f2p + HW, s1);
        }
        ss1[tid] = s1;
        ss2[tid] = make_samp((float)x + f2cx, (float)y + f2cy);
    }
    __syncthreads();

    // ---- phase A1: gather warped features into smem ----
    {
        int px = tid & 63, cg = tid >> 6;          // 4 channel groups x 16 ci
        Samp s1 = ss1[px], s2 = ss2[px];
        int c0 = cg * 16;
        #pragma unroll 4
        for (int ci = c0; ci < c0 + 16; ci++) {
            sin[ci][px]     = bsample(y2p + (size_t)ci*HW, s2);   // a2
            sin[C + ci][px] = bsample(y1p + (size_t)ci*HW, s1);   // a1
        }
    }
    __syncthreads();

    // ---- phase B: 1x1 conv; thread = 4 cols x 4 oc ----
    int tx = tid & 15;                   // cols 4tx..4tx+3
    int og = tid >> 4;                   // oc group 0..15 (oc 4og..4og+3)

    const float* xb = feats + (size_t)(n*T + t) * C * HW + y*W + x0;

    float4 acc[4];
    #pragma unroll
    for (int o = 0; o < 4; o++) {
        float b = __ldg(bfc + og*4 + o);
        acc[o] = make_float4(b, b, b, b);
    }

    #pragma unroll 4
    for (int c = 0; c < 2*C; c++) {
        float4 v = *((const float4*)&sin[c][0] + tx);
        float4 wv = __ldg((const float4*)(g_wfc_t + (size_t)c * C) + og);
        float wo[4] = {wv.x, wv.y, wv.z, wv.w};
        #pragma unroll
        for (int o = 0; o < 4; o++) {
            acc[o].x += v.x*wo[o]; acc[o].y += v.y*wo[o];
            acc[o].z += v.z*wo[o]; acc[o].w += v.w*wo[o];
        }
    }
    #pragma unroll 4
    for (int c = 0; c < C; c++) {
        float4 v = __ldg((const float4*)(xb + (size_t)c*HW) + tx);
        float4 wv = __ldg((const float4*)(g_wfc_t + (size_t)(2*C + c) * C) + og);
        float wo[4] = {wv.x, wv.y, wv.z, wv.w};
        #pragma unroll
        for (int o = 0; o < 4; o++) {
            acc[o].x += v.x*wo[o]; acc[o].y += v.y*wo[o];
            acc[o].z += v.z*wo[o]; acc[o].w += v.w*wo[o];
        }
    }

    float* ob = g_infeat + (size_t)n * C * HW + y*W + x0 + 4*tx;
    #pragma unroll
    for (int o = 0; o < 4; o++)
        *((float4*)(ob + (size_t)(og*4+o)*HW)) = acc[o];
}

// ---------------- kernels 2/3: 3x3 conv, 64->64, SAME, zero pad ----------------
// grid (4, 8, NB*16), block 128; tile 32x16; thread = 4 cols x 1 row x 4 oc
// phase 0: g_infeat -> leaky_relu -> g_h1
// phase 1: g_h1 -> + feats[t] -> d_out[t]
__global__ __launch_bounds__(128, 8) void k_conv3(
    float* __restrict__ outp, const float* __restrict__ bias,
    const float* __restrict__ feats, int phase, int t)
{
    __shared__ float s[8][18][36];             // 20736 B
    int n   = blockIdx.z >> 4;
    int ocg = blockIdx.z & 15;                 // 4 oc per group
    int gx0 = blockIdx.x * 32 - 1;             // halo origin
    int gy0 = blockIdx.y * 16 - 1;
    int tid = threadIdx.x;
    int tx = tid & 7;                          // cols 4tx..4tx+3 (output)
    int ty = tid >> 3;                         // output row 0..15

    const float* inb = (phase ? g_h1 : g_infeat) + (size_t)n * C * HW;
    const float* wt  = phase ? g_w2_t : g_w1_t;

    float4 acc[4];
    #pragma unroll
    for (int o = 0; o < 4; o++) {
        float b = __ldg(bias + ocg*4 + o);
        acc[o] = make_float4(b, b, b, b);
    }

    for (int cc = 0; cc < C; cc += 8) {
        if (cc) __syncthreads();
        // fill 18x34 halo tile for 8 channels
        for (int p = tid; p < 18*34; p += 128) {
            int ry = p / 34, rx = p - ry*34;
            int gy = gy0 + ry, gx = gx0 + rx;
            bool vd = (gy >= 0) && (gy < H) && (gx >= 0) && (gx < W);
            const float* gb = inb + (size_t)cc*HW + gy*W + gx;
            float* sb = &s[0][ry][rx];
            #pragma unroll
            for (int ci = 0; ci < 8; ci++)
                sb[ci*(18*36)] = vd ? gb[ci*HW] : 0.f;
        }
        __syncthreads();

        #pragma unroll 2
        for (int ci = 0; ci < 8; ci++) {
            // taps: 3 rows (ty..ty+2) x 8 cols, 2 LDS.128 per row
            float ta[3][8];
            const float4* s4 = (const float4*)&s[ci][0][0];   // row stride = 9 float4
            #pragma unroll
            for (int r = 0; r < 3; r++) {
                float4 a = s4[(ty + r)*9 + tx];
                float4 b = s4[(ty + r)*9 + tx + 1];
                ta[r][0]=a.x; ta[r][1]=a.y; ta[r][2]=a.z; ta[r][3]=a.w;
                ta[r][4]=b.x; ta[r][5]=b.y; ta[r][6]=b.z; ta[r][7]=b.w;
            }
            #pragma unroll
            for (int ky = 0; ky < 3; ky++) {
                #pragma unroll
                for (int kx = 0; kx < 3; kx++) {
                    float4 wv = __ldg((const float4*)(wt + (size_t)((cc+ci)*9 + ky*3 + kx) * C) + ocg);
                    float wo[4] = {wv.x, wv.y, wv.z, wv.w};
                    #pragma unroll
                    for (int o = 0; o < 4; o++) {
                        acc[o].x += ta[ky][kx+0]*wo[o];
                        acc[o].y += ta[ky][kx+1]*wo[o];
                        acc[o].z += ta[ky][kx+2]*wo[o];
                        acc[o].w += ta[ky][kx+3]*wo[o];
                    }
                }
            }
        }
    }

    int xo = blockIdx.x*32 + 4*tx;
    int yo = blockIdx.y*16 + ty;
    int p0 = yo * W + xo;

    if (phase == 0) {
        float* ob = g_h1 + (size_t)n * C * HW;
        #pragma unroll
        for (int o = 0; o < 4; o++) {
            float4 a = acc[o];
            a.x = a.x > 0.f ? a.x : 0.1f*a.x;  a.y = a.y > 0.f ? a.y : 0.1f*a.y;
            a.z = a.z > 0.f ? a.z : 0.1f*a.z;  a.w = a.w > 0.f ? a.w : 0.1f*a.w;
            *((float4*)(ob + (size_t)(ocg*4+o)*HW + p0)) = a;
        }
    } else {
        size_t base = (size_t)(n*T + t) * C * HW;
        const float* res = feats + base;
        float*       ob  = outp  + base;
        #pragma unroll
        for (int o = 0; o < 4; o++) {
            size_t ch = (size_t)(ocg*4+o)*HW;
            float4 r0 = __ldg((const float4*)(res + ch + p0));
            float4 a = acc[o];
            a.x += r0.x; a.y += r0.y; a.z += r0.z; a.w += r0.w;
            *((float4*)(ob + ch + p0)) = a;
        }
    }
}

// ---------------- launch ----------------
extern "C" void kernel_launch(void* const* d_in, const int* in_sizes, int n_in,
                              void* d_out, int out_size) {
    const float* feats = (const float*)d_in[0];
    const float* flows = (const float*)d_in[1];
    const float* bfc   = (const float*)d_in[3];
    const float* b1    = (const float*)d_in[5];
    const float* b2    = (const float*)d_in[7];
    float* out = (float*)d_out;
    (void)in_sizes; (void)n_in; (void)out_size;

    k_prep<<<(C*9*C + 255)/256, 256>>>((const float*)d_in[2],
                                       (const float*)d_in[4],
                                       (const float*)d_in[6]);

    dim3 cgrid(4, 8, NB*16);
    for (int t = 0; t < T; t++) {
        k_wfc<<<NB*256, 256>>>(feats, flows, out, bfc, t);
        k_conv3<<<cgrid, 128>>>(out, b1, feats, 0, t);
        k_conv3<<<cgrid, 128>>>(out, b2, feats, 1, t);
    }
}

// round 10
// speedup vs baseline: 2.8161x; 1.0763x over previous
#include <cuda_runtime.h>

#define NB 2
#define T  16
#define C  64
#define H  128
#define W  128
#define HW (H*W)

// ---------------- scratch (no allocation allowed) ----------------
__device__ float g_infeat[NB*C*HW];     // 1x1-conv output per step
__device__ float g_h1[NB*C*HW];         // conv1+leaky output per step
__device__ float g_wfc_t[3*C*C];        // [192][64]  (c-major, oc contiguous)
__device__ float g_w1_t[C*9*C];         // [(ci*9+k)][64]
__device__ float g_w2_t[C*9*C];

// ---------------- weight transposition ----------------
__global__ void k_prep(const float* __restrict__ Wfc,
                       const float* __restrict__ W1,
                       const float* __restrict__ W2) {
    int i = blockIdx.x * blockDim.x + threadIdx.x;
    if (i < 3*C*C) {                      // 12288
        int c = i >> 6, oc = i & 63;      // Wfc layout: [oc][3C]
        g_wfc_t[i] = Wfc[oc * (3*C) + c];
    }
    if (i < C*9*C) {                      // 36864
        int ck = i >> 6, oc = i & 63;
        int ci = ck / 9, k = ck % 9;      // W layout: [oc][ci][3][3]
        g_w1_t[i] = W1[(oc*C + ci)*9 + k];
        g_w2_t[i] = W2[(oc*C + ci)*9 + k];
    }
}

// ---------------- bilinear sampling helpers ----------------
struct Samp { int o00, o01, o10, o11; float w00, w01, w10, w11; };

__device__ __forceinline__ Samp make_samp(float gx, float gy) {
    float x0f = floorf(gx), y0f = floorf(gy);
    float wx = gx - x0f, wy = gy - y0f;
    int x0 = (int)x0f, y0 = (int)y0f;
    int x1 = x0 + 1,  y1 = y0 + 1;
    bool vx0 = (x0 >= 0) && (x0 < W), vx1 = (x1 >= 0) && (x1 < W);
    bool vy0 = (y0 >= 0) && (y0 < H), vy1 = (y1 >= 0) && (y1 < H);
    int cx0 = min(max(x0, 0), W-1), cx1 = min(max(x1, 0), W-1);
    int cy0 = min(max(y0, 0), H-1), cy1 = min(max(y1, 0), H-1);
    Samp s;
    s.o00 = cy0*W + cx0; s.o01 = cy0*W + cx1;
    s.o10 = cy1*W + cx0; s.o11 = cy1*W + cx1;
    s.w00 = (vx0 && vy0) ? (1.f-wx)*(1.f-wy) : 0.f;
    s.w01 = (vx1 && vy0) ? wx*(1.f-wy)       : 0.f;
    s.w10 = (vx0 && vy1) ? (1.f-wx)*wy       : 0.f;
    s.w11 = (vx1 && vy1) ? wx*wy             : 0.f;
    return s;
}

__device__ __forceinline__ float bsample(const float* __restrict__ p, const Samp& s) {
    return p[s.o00]*s.w00 + p[s.o01]*s.w01 + p[s.o10]*s.w10 + p[s.o11]*s.w11;
}

// ---------------- kernel 1: fused flow warp + 1x1 conv (192->64) ----------------
// grid NB*512 (CTA = 32-pixel strip, all 64 oc), block 128
__global__ __launch_bounds__(128) void k_wfc(
    const float* __restrict__ feats, const float* __restrict__ flows,
    const float* __restrict__ out,   const float* __restrict__ bfc, int t)
{
    __shared__ float sin[2*C][32];       // a2: ch 0..63, a1: ch 64..127 (16 KB)
    __shared__ Samp ss1[32], ss2[32];    // 2 KB

    int bid = blockIdx.x;
    int n = bid >> 9, rem = bid & 511;
    int y = rem >> 2, x0 = (rem & 3) * 32;
    int tid = threadIdx.x;

    const float* y1p = (t >= 1) ? out   + (size_t)(n*T + (t-1)) * C * HW
                                : feats + (size_t)(n*T)         * C * HW;
    const float* y2p = (t >= 2) ? out   + (size_t)(n*T + (t-2)) * C * HW
                                : feats + (size_t)(n*T)         * C * HW;

    // ---- phase A0: per-pixel Samp (32 threads) ----
    if (tid < 32) {
        int x = x0 + tid;
        int pix = y * W + x;
        float f1x = 0.f, f1y = 0.f;
        if (t >= 1) {
            const float* f1p = flows + (size_t)(n*T + (t-1)) * 2 * HW;
            f1x = f1p[pix]; f1y = f1p[HW + pix];
        }
        Samp s1 = make_samp((float)x + f1x, (float)y + f1y);
        float f2cx = f1x, f2cy = f1y;    // t<2: f2=0 -> warp(f2)=0 -> f2c=f1
        if (t >= 2) {
            const float* f2p = flows + (size_t)(n*T + (t-2)) * 2 * HW;
            f2cx += bsample(f2p,      s1);
            f2cy += bsample(f2p + HW, s1);
        }
        ss1[tid] = s1;
        ss2[tid] = make_samp((float)x + f2cx, (float)y + f2cy);
    }
    __syncthreads();

    // ---- phase A1: gather warped features into smem ----
    {
        int px = tid & 31, cg = tid >> 5;          // 4 channel groups x 16 ci
        Samp s1 = ss1[px], s2 = ss2[px];
        int c0 = cg * 16;
        #pragma unroll 4
        for (int ci = c0; ci < c0 + 16; ci++) {
            sin[ci][px]     = bsample(y2p + (size_t)ci*HW, s2);   // a2
            sin[C + ci][px] = bsample(y1p + (size_t)ci*HW, s1);   // a1
        }
    }
    __syncthreads();

    // ---- phase B: 1x1 conv; thread = 4 cols x 4 oc ----
    int tx = tid & 7;                    // cols 4tx..4tx+3
    int og = tid >> 3;                   // oc group 0..15 (oc 4og..4og+3)

    const float* xb = feats + (size_t)(n*T + t) * C * HW + y*W + x0;

    float4 acc[4];
    #pragma unroll
    for (int o = 0; o < 4; o++) {
        float b = __ldg(bfc + og*4 + o);
        acc[o] = make_float4(b, b, b, b);
    }

    #pragma unroll 4
    for (int c = 0; c < 2*C; c++) {
        float4 v = *((const float4*)&sin[c][0] + tx);
        float4 wv = __ldg((const float4*)(g_wfc_t + (size_t)c * C) + og);
        float wo[4] = {wv.x, wv.y, wv.z, wv.w};
        #pragma unroll
        for (int o = 0; o < 4; o++) {
            acc[o].x += v.x*wo[o]; acc[o].y += v.y*wo[o];
            acc[o].z += v.z*wo[o]; acc[o].w += v.w*wo[o];
        }
    }
    #pragma unroll 4
    for (int c = 0; c < C; c++) {
        float4 v = __ldg((const float4*)(xb + (size_t)c*HW) + tx);
        float4 wv = __ldg((const float4*)(g_wfc_t + (size_t)(2*C + c) * C) + og);
        float wo[4] = {wv.x, wv.y, wv.z, wv.w};
        #pragma unroll
        for (int o = 0; o < 4; o++) {
            acc[o].x += v.x*wo[o]; acc[o].y += v.y*wo[o];
            acc[o].z += v.z*wo[o]; acc[o].w += v.w*wo[o];
        }
    }

    float* ob = g_infeat + (size_t)n * C * HW + y*W + x0 + 4*tx;
    #pragma unroll
    for (int o = 0; o < 4; o++)
        *((float4*)(ob + (size_t)(og*4+o)*HW)) = acc[o];
}

// ---------------- kernels 2/3: 3x3 conv, 64->64, SAME, zero pad ----------------
// grid (4, 8, NB*16), block 64 (8tx x 8ty); tile 32x16
// thread = 4 cols x 2 rows x 4 oc; taps via LDS.128, 4 rows reused for 2 outputs
// phase 0: g_infeat -> leaky_relu -> g_h1
// phase 1: g_h1 -> + feats[t] -> d_out[t]
__global__ __launch_bounds__(64, 8) void k_conv3(
    float* __restrict__ outp, const float* __restrict__ bias,
    const float* __restrict__ feats, int phase, int t)
{
    __shared__ float s[8][18][36];             // 20736 B
    int n   = blockIdx.z >> 4;
    int ocg = blockIdx.z & 15;                 // 4 oc per group
    int gx0 = blockIdx.x * 32 - 1;             // halo origin
    int gy0 = blockIdx.y * 16 - 1;
    int tid = threadIdx.x;
    int tx = tid & 7;                          // cols 4tx..4tx+3 (output)
    int ty = tid >> 3;                         // 0..7 -> output rows 2ty, 2ty+1

    const float* inb = (phase ? g_h1 : g_infeat) + (size_t)n * C * HW;
    const float* wt  = phase ? g_w2_t : g_w1_t;

    float4 acc[2][4];                          // [row][oc], lanes = 4 cols
    #pragma unroll
    for (int o = 0; o < 4; o++) {
        float b = __ldg(bias + ocg*4 + o);
        acc[0][o] = make_float4(b, b, b, b);
        acc[1][o] = acc[0][o];
    }

    for (int cc = 0; cc < C; cc += 8) {
        if (cc) __syncthreads();
        // fill 18x34 halo tile for 8 channels
        for (int p = tid; p < 18*34; p += 64) {
            int ry = p / 34, rx = p - ry*34;
            int gy = gy0 + ry, gx = gx0 + rx;
            bool vd = (gy >= 0) && (gy < H) && (gx >= 0) && (gx < W);
            const float* gb = inb + (size_t)cc*HW + gy*W + gx;
            float* sb = &s[0][ry][rx];
            #pragma unroll
            for (int ci = 0; ci < 8; ci++)
                sb[ci*(18*36)] = vd ? gb[ci*HW] : 0.f;
        }
        __syncthreads();

        #pragma unroll 2
        for (int ci = 0; ci < 8; ci++) {
            // taps: 4 rows (2ty..2ty+3) x 8 cols, 2 LDS.128 per row
            float ta[4][8];
            const float4* s4 = (const float4*)&s[ci][0][0];   // row stride = 9 float4
            #pragma unroll
            for (int r = 0; r < 4; r++) {
                float4 a = s4[(2*ty + r)*9 + tx];
                float4 b = s4[(2*ty + r)*9 + tx + 1];
                ta[r][0]=a.x; ta[r][1]=a.y; ta[r][2]=a.z; ta[r][3]=a.w;
                ta[r][4]=b.x; ta[r][5]=b.y; ta[r][6]=b.z; ta[r][7]=b.w;
            }
            #pragma unroll
            for (int ky = 0; ky < 3; ky++) {
                #pragma unroll
                for (int kx = 0; kx < 3; kx++) {
                    float4 wv = __ldg((const float4*)(wt + (size_t)((cc+ci)*9 + ky*3 + kx) * C) + ocg);
                    float wo[4] = {wv.x, wv.y, wv.z, wv.w};
                    #pragma unroll
                    for (int pr = 0; pr < 2; pr++) {
                        #pragma unroll
                        for (int o = 0; o < 4; o++) {
                            acc[pr][o].x += ta[pr+ky][kx+0]*wo[o];
                            acc[pr][o].y += ta[pr+ky][kx+1]*wo[o];
                            acc[pr][o].z += ta[pr+ky][kx+2]*wo[o];
                            acc[pr][o].w += ta[pr+ky][kx+3]*wo[o];
                        }
                    }
                }
            }
        }
    }

    int xo = blockIdx.x*32 + 4*tx;
    int yo = blockIdx.y*16 + 2*ty;
    int p0 = yo * W + xo;
    int p1 = p0 + W;

    if (phase == 0) {
        float* ob = g_h1 + (size_t)n * C * HW;
        #pragma unroll
        for (int o = 0; o < 4; o++) {
            float4 a = acc[0][o], b = acc[1][o];
            a.x = a.x > 0.f ? a.x : 0.1f*a.x;  a.y = a.y > 0.f ? a.y : 0.1f*a.y;
            a.z = a.z > 0.f ? a.z : 0.1f*a.z;  a.w = a.w > 0.f ? a.w : 0.1f*a.w;
            b.x = b.x > 0.f ? b.x : 0.1f*b.x;  b.y = b.y > 0.f ? b.y : 0.1f*b.y;
            b.z = b.z > 0.f ? b.z : 0.1f*b.z;  b.w = b.w > 0.f ? b.w : 0.1f*b.w;
            *((float4*)(ob + (size_t)(ocg*4+o)*HW + p0)) = a;
            *((float4*)(ob + (size_t)(ocg*4+o)*HW + p1)) = b;
        }
    } else {
        size_t base = (size_t)(n*T + t) * C * HW;
        const float* res = feats + base;
        float*       ob  = outp  + base;
        #pragma unroll
        for (int o = 0; o < 4; o++) {
            size_t ch = (size_t)(ocg*4+o)*HW;
            float4 r0 = __ldg((const float4*)(res + ch + p0));
            float4 r1 = __ldg((const float4*)(res + ch + p1));
            float4 a = acc[0][o], b = acc[1][o];
            a.x += r0.x; a.y += r0.y; a.z += r0.z; a.w += r0.w;
            b.x += r1.x; b.y += r1.y; b.z += r1.z; b.w += r1.w;
            *((float4*)(ob + ch + p0)) = a;
            *((float4*)(ob + ch + p1)) = b;
        }
    }
}

// ---------------- launch ----------------
extern "C" void kernel_launch(void* const* d_in, const int* in_sizes, int n_in,
                              void* d_out, int out_size) {
    const float* feats = (const float*)d_in[0];
    const float* flows = (const float*)d_in[1];
    const float* bfc   = (const float*)d_in[3];
    const float* b1    = (const float*)d_in[5];
    const float* b2    = (const float*)d_in[7];
    float* out = (float*)d_out;
    (void)in_sizes; (void)n_in; (void)out_size;

    k_prep<<<(C*9*C + 255)/256, 256>>>((const float*)d_in[2],
                                       (const float*)d_in[4],
                                       (const float*)d_in[6]);

    dim3 cgrid(4, 8, NB*16);
    for (int t = 0; t < T; t++) {
        k_wfc<<<NB*512, 128>>>(feats, flows, out, bfc, t);
        k_conv3<<<cgrid, 64>>>(out, b1, feats, 0, t);
        k_conv3<<<cgrid, 64>>>(out, b2, feats, 1, t);
    }
}

// round 11
// speedup vs baseline: 2.8455x; 1.0104x over previous
#include <cuda_runtime.h>
#include <cstdint>

#define NB 2
#define T  16
#define C  64
#define H  128
#define W  128
#define HW (H*W)

#define CH4 4                 // ci per pipeline stage (conv3)
#define STG_F (CH4*18*36)     // floats per stage

// ---------------- scratch (no allocation allowed) ----------------
__device__ float g_infeat[NB*C*HW];     // 1x1-conv output per step
__device__ float g_h1[NB*C*HW];         // conv1+leaky output per step
__device__ float g_wfc_t[3*C*C];        // [192][64]  (c-major, oc contiguous)
__device__ float g_w1_t[C*9*C];         // [(ci*9+k)][64]
__device__ float g_w2_t[C*9*C];

// ---------------- async-copy helpers ----------------
__device__ __forceinline__ uint32_t smem_u32(const void* p) {
    uint32_t a;
    asm("{ .reg .u64 t; cvta.to.shared.u64 t, %1; cvt.u32.u64 %0, t; }"
        : "=r"(a) : "l"(p));
    return a;
}
__device__ __forceinline__ void cp4(uint32_t saddr, const void* g, bool vd) {
    int sz = vd ? 4 : 0;
    asm volatile("cp.async.ca.shared.global [%0], [%1], 4, %2;"
                 :: "r"(saddr), "l"(g), "r"(sz) : "memory");
}
#define CP_COMMIT() asm volatile("cp.async.commit_group;" ::: "memory")
#define CP_WAIT1()  asm volatile("cp.async.wait_group 1;" ::: "memory")
#define CP_WAIT0()  asm volatile("cp.async.wait_group 0;" ::: "memory")

// ---------------- weight transposition ----------------
__global__ void k_prep(const float* __restrict__ Wfc,
                       const float* __restrict__ W1,
                       const float* __restrict__ W2) {
    int i = blockIdx.x * blockDim.x + threadIdx.x;
    if (i < 3*C*C) {                      // 12288
        int c = i >> 6, oc = i & 63;      // Wfc layout: [oc][3C]
        g_wfc_t[i] = Wfc[oc * (3*C) + c];
    }
    if (i < C*9*C) {                      // 36864
        int ck = i >> 6, oc = i & 63;
        int ci = ck / 9, k = ck % 9;      // W layout: [oc][ci][3][3]
        g_w1_t[i] = W1[(oc*C + ci)*9 + k];
        g_w2_t[i] = W2[(oc*C + ci)*9 + k];
    }
}

// ---------------- bilinear sampling helpers ----------------
struct Samp { int o00, o01, o10, o11; float w00, w01, w10, w11; };

__device__ __forceinline__ Samp make_samp(float gx, float gy) {
    float x0f = floorf(gx), y0f = floorf(gy);
    float wx = gx - x0f, wy = gy - y0f;
    int x0 = (int)x0f, y0 = (int)y0f;
    int x1 = x0 + 1,  y1 = y0 + 1;
    bool vx0 = (x0 >= 0) && (x0 < W), vx1 = (x1 >= 0) && (x1 < W);
    bool vy0 = (y0 >= 0) && (y0 < H), vy1 = (y1 >= 0) && (y1 < H);
    int cx0 = min(max(x0, 0), W-1), cx1 = min(max(x1, 0), W-1);
    int cy0 = min(max(y0, 0), H-1), cy1 = min(max(y1, 0), H-1);
    Samp s;
    s.o00 = cy0*W + cx0; s.o01 = cy0*W + cx1;
    s.o10 = cy1*W + cx0; s.o11 = cy1*W + cx1;
    s.w00 = (vx0 && vy0) ? (1.f-wx)*(1.f-wy) : 0.f;
    s.w01 = (vx1 && vy0) ? wx*(1.f-wy)       : 0.f;
    s.w10 = (vx0 && vy1) ? (1.f-wx)*wy       : 0.f;
    s.w11 = (vx1 && vy1) ? wx*wy             : 0.f;
    return s;
}

__device__ __forceinline__ float bsample(const float* __restrict__ p, const Samp& s) {
    return p[s.o00]*s.w00 + p[s.o01]*s.w01 + p[s.o10]*s.w10 + p[s.o11]*s.w11;
}

// ---------------- kernel 1: fused flow warp + 1x1 conv (192->64) ----------------
// grid NB*512 (CTA = 32-pixel strip, all 64 oc), block 128
__global__ __launch_bounds__(128) void k_wfc(
    const float* __restrict__ feats, const float* __restrict__ flows,
    const float* __restrict__ out,   const float* __restrict__ bfc, int t)
{
    __shared__ float sin[2*C][32];       // a2: ch 0..63, a1: ch 64..127 (16 KB)
    __shared__ Samp ss1[32], ss2[32];    // 2 KB

    int bid = blockIdx.x;
    int n = bid >> 9, rem = bid & 511;
    int y = rem >> 2, x0 = (rem & 3) * 32;
    int tid = threadIdx.x;

    const float* y1p = (t >= 1) ? out   + (size_t)(n*T + (t-1)) * C * HW
                                : feats + (size_t)(n*T)         * C * HW;
    const float* y2p = (t >= 2) ? out   + (size_t)(n*T + (t-2)) * C * HW
                                : feats + (size_t)(n*T)         * C * HW;

    // ---- phase A0: per-pixel Samp (32 threads) ----
    if (tid < 32) {
        int x = x0 + tid;
        int pix = y * W + x;
        float f1x = 0.f, f1y = 0.f;
        if (t >= 1) {
            const float* f1p = flows + (size_t)(n*T + (t-1)) * 2 * HW;
            f1x = f1p[pix]; f1y = f1p[HW + pix];
        }
        Samp s1 = make_samp((float)x + f1x, (float)y + f1y);
        float f2cx = f1x, f2cy = f1y;    // t<2: f2=0 -> warp(f2)=0 -> f2c=f1
        if (t >= 2) {
            const float* f2p = flows + (size_t)(n*T + (t-2)) * 2 * HW;
            f2cx += bsample(f2p,      s1);
            f2cy += bsample(f2p + HW, s1);
        }
        ss1[tid] = s1;
        ss2[tid] = make_samp((float)x + f2cx, (float)y + f2cy);
    }
    __syncthreads();

    // ---- phase A1: gather warped features into smem ----
    {
        int px = tid & 31, cg = tid >> 5;          // 4 channel groups x 16 ci
        Samp s1 = ss1[px], s2 = ss2[px];
        int c0 = cg * 16;
        #pragma unroll 4
        for (int ci = c0; ci < c0 + 16; ci++) {
            sin[ci][px]     = bsample(y2p + (size_t)ci*HW, s2);   // a2
            sin[C + ci][px] = bsample(y1p + (size_t)ci*HW, s1);   // a1
        }
    }
    __syncthreads();

    // ---- phase B: 1x1 conv; thread = 4 cols x 4 oc ----
    int tx = tid & 7;                    // cols 4tx..4tx+3
    int og = tid >> 3;                   // oc group 0..15 (oc 4og..4og+3)

    const float* xb = feats + (size_t)(n*T + t) * C * HW + y*W + x0;

    float4 acc[4];
    #pragma unroll
    for (int o = 0; o < 4; o++) {
        float b = __ldg(bfc + og*4 + o);
        acc[o] = make_float4(b, b, b, b);
    }

    #pragma unroll 4
    for (int c = 0; c < 2*C; c++) {
        float4 v = *((const float4*)&sin[c][0] + tx);
        float4 wv = __ldg((const float4*)(g_wfc_t + (size_t)c * C) + og);
        float wo[4] = {wv.x, wv.y, wv.z, wv.w};
        #pragma unroll
        for (int o = 0; o < 4; o++) {
            acc[o].x += v.x*wo[o]; acc[o].y += v.y*wo[o];
            acc[o].z += v.z*wo[o]; acc[o].w += v.w*wo[o];
        }
    }
    #pragma unroll 4
    for (int c = 0; c < C; c++) {
        float4 v = __ldg((const float4*)(xb + (size_t)c*HW) + tx);
        float4 wv = __ldg((const float4*)(g_wfc_t + (size_t)(2*C + c) * C) + og);
        float wo[4] = {wv.x, wv.y, wv.z, wv.w};
        #pragma unroll
        for (int o = 0; o < 4; o++) {
            acc[o].x += v.x*wo[o]; acc[o].y += v.y*wo[o];
            acc[o].z += v.z*wo[o]; acc[o].w += v.w*wo[o];
        }
    }

    float* ob = g_infeat + (size_t)n * C * HW + y*W + x0 + 4*tx;
    #pragma unroll
    for (int o = 0; o < 4; o++)
        *((float4*)(ob + (size_t)(og*4+o)*HW)) = acc[o];
}

// ---------------- kernels 2/3: 3x3 conv, 64->64, SAME, zero pad ----------------
// grid (4, 8, NB*16), block 64 (8tx x 8ty); tile 32x16
// thread = 4 cols x 2 rows x 4 oc; cp.async double-buffered input stages;
// weights staged in smem (broadcast LDS)
// phase 0: g_infeat -> leaky_relu -> g_h1
// phase 1: g_h1 -> + feats[t] -> d_out[t]
__global__ __launch_bounds__(64, 7) void k_conv3(
    float* __restrict__ outp, const float* __restrict__ bias,
    const float* __restrict__ feats, int phase, int t)
{
    __shared__ float s[2][CH4][18][36];        // 20736 B (2 stages)
    __shared__ float4 wsm[C*9];                // 9216 B: [(ci*9+k)] -> this ocg's 4 oc
    int n   = blockIdx.z >> 4;
    int ocg = blockIdx.z & 15;                 // 4 oc per group
    int gx0 = blockIdx.x * 32 - 1;             // halo origin
    int gy0 = blockIdx.y * 16 - 1;
    int tid = threadIdx.x;
    int tx = tid & 7;                          // cols 4tx..4tx+3 (output)
    int ty = tid >> 3;                         // 0..7 -> output rows 2ty, 2ty+1

    const float* inb = (phase ? g_h1 : g_infeat) + (size_t)n * C * HW;
    const float* wt  = phase ? g_w2_t : g_w1_t;

    // ---- stage this ocg's weights into smem (9 float4 loads/thread) ----
    for (int i = tid; i < C*9; i += 64)
        wsm[i] = __ldg((const float4*)(wt + (size_t)i * C) + ocg);

    // ---- precompute fill tables: 10 positions/thread, no div in hot loop ----
    bool finA[10], fvdA[10];
    int  gofA[10], sofA[10];
    #pragma unroll
    for (int q = 0; q < 10; q++) {
        int p = tid + q*64;
        bool inr = (p < 18*34);
        int ry = p / 34, rx = p - ry*34;
        int gy = gy0 + ry, gx = gx0 + rx;
        finA[q] = inr;
        bool vd = inr && (gy >= 0) && (gy < H) && (gx >= 0) && (gx < W);
        fvdA[q] = vd;
        gofA[q] = vd ? (gy*W + gx) : 0;
        sofA[q] = ry*36 + rx;
    }
    uint32_t s_u32 = smem_u32(&s[0][0][0][0]);

    float4 acc[2][4];                          // [row][oc], lanes = 4 cols
    #pragma unroll
    for (int o = 0; o < 4; o++) {
        float b = __ldg(bias + ocg*4 + o);
        acc[0][o] = make_float4(b, b, b, b);
        acc[1][o] = acc[0][o];
    }

    // ---- async fill of one stage ----
    auto fill = [&](int st, int cc) {
        const float* cb = inb + (size_t)cc * HW;
        uint32_t sb = s_u32 + (uint32_t)st * (STG_F*4);
        #pragma unroll
        for (int q = 0; q < 10; q++) {
            if (finA[q]) {
                uint32_t sa = sb + (uint32_t)sofA[q]*4;
                const float* g = cb + gofA[q];
                #pragma unroll
                for (int ci = 0; ci < CH4; ci++)
                    cp4(sa + ci*(18*36*4), g + (size_t)ci*HW, fvdA[q]);
            }
        }
    };

    fill(0, 0); CP_COMMIT();

    for (int k = 0; k < C/CH4; k++) {
        int cur = k & 1;
        int cc = k * CH4;
        if (k < C/CH4 - 1) { fill(cur ^ 1, cc + CH4); CP_COMMIT(); CP_WAIT1(); }
        else               { CP_WAIT0(); }
        __syncthreads();

        #pragma unroll
        for (int ci = 0; ci < CH4; ci++) {
            // taps: 4 rows (2ty..2ty+3) x 8 cols, 2 LDS.128 per row
            float ta[4][8];
            const float4* s4 = (const float4*)&s[cur][ci][0][0];  // row stride = 9 float4
            #pragma unroll
            for (int r = 0; r < 4; r++) {
                float4 a = s4[(2*ty + r)*9 + tx];
                float4 b = s4[(2*ty + r)*9 + tx + 1];
                ta[r][0]=a.x; ta[r][1]=a.y; ta[r][2]=a.z; ta[r][3]=a.w;
                ta[r][4]=b.x; ta[r][5]=b.y; ta[r][6]=b.z; ta[r][7]=b.w;
            }
            #pragma unroll
            for (int ky = 0; ky < 3; ky++) {
                #pragma unroll
                for (int kx = 0; kx < 3; kx++) {
                    float4 wv = wsm[(cc+ci)*9 + ky*3 + kx];
                    float wo[4] = {wv.x, wv.y, wv.z, wv.w};
                    #pragma unroll
                    for (int pr = 0; pr < 2; pr++) {
                        #pragma unroll
                        for (int o = 0; o < 4; o++) {
                            acc[pr][o].x += ta[pr+ky][kx+0]*wo[o];
                            acc[pr][o].y += ta[pr+ky][kx+1]*wo[o];
                            acc[pr][o].z += ta[pr+ky][kx+2]*wo[o];
                            acc[pr][o].w += ta[pr+ky][kx+3]*wo[o];
                        }
                    }
                }
            }
        }
        __syncthreads();
    }

    int xo = blockIdx.x*32 + 4*tx;
    int yo = blockIdx.y*16 + 2*ty;
    int p0 = yo * W + xo;
    int p1 = p0 + W;

    if (phase == 0) {
        float* ob = g_h1 + (size_t)n * C * HW;
        #pragma unroll
        for (int o = 0; o < 4; o++) {
            float4 a = acc[0][o], b = acc[1][o];
            a.x = a.x > 0.f ? a.x : 0.1f*a.x;  a.y = a.y > 0.f ? a.y : 0.1f*a.y;
            a.z = a.z > 0.f ? a.z : 0.1f*a.z;  a.w = a.w > 0.f ? a.w : 0.1f*a.w;
            b.x = b.x > 0.f ? b.x : 0.1f*b.x;  b.y = b.y > 0.f ? b.y : 0.1f*b.y;
            b.z = b.z > 0.f ? b.z : 0.1f*b.z;  b.w = b.w > 0.f ? b.w : 0.1f*b.w;
            *((float4*)(ob + (size_t)(ocg*4+o)*HW + p0)) = a;
            *((float4*)(ob + (size_t)(ocg*4+o)*HW + p1)) = b;
        }
    } else {
        size_t base = (size_t)(n*T + t) * C * HW;
        const float* res = feats + base;
        float*       ob  = outp  + base;
        #pragma unroll
        for (int o = 0; o < 4; o++) {
            size_t ch = (size_t)(ocg*4+o)*HW;
            float4 r0 = __ldg((const float4*)(res + ch + p0));
            float4 r1 = __ldg((const float4*)(res + ch + p1));
            float4 a = acc[0][o], b = acc[1][o];
            a.x += r0.x; a.y += r0.y; a.z += r0.z; a.w += r0.w;
            b.x += r1.x; b.y += r1.y; b.z += r1.z; b.w += r1.w;
            *((float4*)(ob + ch + p0)) = a;
            *((float4*)(ob + ch + p1)) = b;
        }
    }
}

// ---------------- launch ----------------
extern "C" void kernel_launch(void* const* d_in, const int* in_sizes, int n_in,
                              void* d_out, int out_size) {
    const float* feats = (const float*)d_in[0];
    const float* flows = (const float*)d_in[1];
    const float* bfc   = (const float*)d_in[3];
    const float* b1    = (const float*)d_in[5];
    const float* b2    = (const float*)d_in[7];
    float* out = (float*)d_out;
    (void)in_sizes; (void)n_in; (void)out_size;

    k_prep<<<(C*9*C + 255)/256, 256>>>((const float*)d_in[2],
                                       (const float*)d_in[4],
                                       (const float*)d_in[6]);

    dim3 cgrid(4, 8, NB*16);
    for (int t = 0; t < T; t++) {
        k_wfc<<<NB*512, 128>>>(feats, flows, out, bfc, t);
        k_conv3<<<cgrid, 64>>>(out, b1, feats, 0, t);
        k_conv3<<<cgrid, 64>>>(out, b2, feats, 1, t);
    }
}

// round 12
// speedup vs baseline: 2.8474x; 1.0007x over previous
#include <cuda_runtime.h>
#include <cstdint>

#define NB 2
#define T  16
#define C  64
#define H  128
#define W  128
#define HW (H*W)

#define CH4 4                 // ci per pipeline stage (conv3)
#define STG_F (CH4*18*36)     // floats per stage

// ---------------- scratch (no allocation allowed) ----------------
__device__ float g_infeat[NB*C*HW];     // 1x1-conv output per step
__device__ float g_h1[NB*C*HW];         // conv1+leaky output per step
__device__ float g_wfc_t[3*C*C];        // [192][64]  (c-major, oc contiguous)
__device__ float g_w1_t[C*9*C];         // [(ci*9+k)][64]
__device__ float g_w2_t[C*9*C];

// ---------------- async-copy helpers ----------------
__device__ __forceinline__ uint32_t smem_u32(const void* p) {
    uint32_t a;
    asm("{ .reg .u64 t; cvta.to.shared.u64 t, %1; cvt.u32.u64 %0, t; }"
        : "=r"(a) : "l"(p));
    return a;
}
__device__ __forceinline__ void cp4(uint32_t saddr, const void* g, bool vd) {
    int sz = vd ? 4 : 0;
    asm volatile("cp.async.ca.shared.global [%0], [%1], 4, %2;"
                 :: "r"(saddr), "l"(g), "r"(sz) : "memory");
}
#define CP_COMMIT() asm volatile("cp.async.commit_group;" ::: "memory")
#define CP_WAIT1()  asm volatile("cp.async.wait_group 1;" ::: "memory")
#define CP_WAIT0()  asm volatile("cp.async.wait_group 0;" ::: "memory")

// ---------------- weight transposition ----------------
__global__ void k_prep(const float* __restrict__ Wfc,
                       const float* __restrict__ W1,
                       const float* __restrict__ W2) {
    int i = blockIdx.x * blockDim.x + threadIdx.x;
    if (i < 3*C*C) {                      // 12288
        int c = i >> 6, oc = i & 63;      // Wfc layout: [oc][3C]
        g_wfc_t[i] = Wfc[oc * (3*C) + c];
    }
    if (i < C*9*C) {                      // 36864
        int ck = i >> 6, oc = i & 63;
        int ci = ck / 9, k = ck % 9;      // W layout: [oc][ci][3][3]
        g_w1_t[i] = W1[(oc*C + ci)*9 + k];
        g_w2_t[i] = W2[(oc*C + ci)*9 + k];
    }
}

// ---------------- bilinear sampling helpers ----------------
struct Samp { int o00, o01, o10, o11; float w00, w01, w10, w11; };

__device__ __forceinline__ Samp make_samp(float gx, float gy) {
    float x0f = floorf(gx), y0f = floorf(gy);
    float wx = gx - x0f, wy = gy - y0f;
    int x0 = (int)x0f, y0 = (int)y0f;
    int x1 = x0 + 1,  y1 = y0 + 1;
    bool vx0 = (x0 >= 0) && (x0 < W), vx1 = (x1 >= 0) && (x1 < W);
    bool vy0 = (y0 >= 0) && (y0 < H), vy1 = (y1 >= 0) && (y1 < H);
    int cx0 = min(max(x0, 0), W-1), cx1 = min(max(x1, 0), W-1);
    int cy0 = min(max(y0, 0), H-1), cy1 = min(max(y1, 0), H-1);
    Samp s;
    s.o00 = cy0*W + cx0; s.o01 = cy0*W + cx1;
    s.o10 = cy1*W + cx0; s.o11 = cy1*W + cx1;
    s.w00 = (vx0 && vy0) ? (1.f-wx)*(1.f-wy) : 0.f;
    s.w01 = (vx1 && vy0) ? wx*(1.f-wy)       : 0.f;
    s.w10 = (vx0 && vy1) ? (1.f-wx)*wy       : 0.f;
    s.w11 = (vx1 && vy1) ? wx*wy             : 0.f;
    return s;
}

__device__ __forceinline__ float bsample(const float* __restrict__ p, const Samp& s) {
    return p[s.o00]*s.w00 + p[s.o01]*s.w01 + p[s.o10]*s.w10 + p[s.o11]*s.w11;
}

// ---------------- kernel 1: fused flow warp + 1x1 conv (192->64) ----------------
// grid NB*512 (CTA = 32-pixel strip, all 64 oc), block 128
__global__ __launch_bounds__(128) void k_wfc(
    const float* __restrict__ feats, const float* __restrict__ flows,
    const float* __restrict__ out,   const float* __restrict__ bfc, int t)
{
    __shared__ float sin[2*C][32];       // a2: ch 0..63, a1: ch 64..127 (16 KB)
    __shared__ Samp ss1[32], ss2[32];    // 2 KB

    int bid = blockIdx.x;
    int n = bid >> 9, rem = bid & 511;
    int y = rem >> 2, x0 = (rem & 3) * 32;
    int tid = threadIdx.x;

    const float* y1p = (t >= 1) ? out   + (size_t)(n*T + (t-1)) * C * HW
                                : feats + (size_t)(n*T)         * C * HW;
    const float* y2p = (t >= 2) ? out   + (size_t)(n*T + (t-2)) * C * HW
                                : feats + (size_t)(n*T)         * C * HW;

    // ---- phase A0: per-pixel Samp (32 threads) ----
    if (tid < 32) {
        int x = x0 + tid;
        int pix = y * W + x;
        float f1x = 0.f, f1y = 0.f;
        if (t >= 1) {
            const float* f1p = flows + (size_t)(n*T + (t-1)) * 2 * HW;
            f1x = f1p[pix]; f1y = f1p[HW + pix];
        }
        Samp s1 = make_samp((float)x + f1x, (float)y + f1y);
        float f2cx = f1x, f2cy = f1y;    // t<2: f2=0 -> warp(f2)=0 -> f2c=f1
        if (t >= 2) {
            const float* f2p = flows + (size_t)(n*T + (t-2)) * 2 * HW;
            f2cx += bsample(f2p,      s1);
            f2cy += bsample(f2p + HW, s1);
        }
        ss1[tid] = s1;
        ss2[tid] = make_samp((float)x + f2cx, (float)y + f2cy);
    }
    __syncthreads();

    // ---- phase A1: gather warped features into smem ----
    {
        int px = tid & 31, cg = tid >> 5;          // 4 channel groups x 16 ci
        Samp s1 = ss1[px], s2 = ss2[px];
        int c0 = cg * 16;
        #pragma unroll 4
        for (int ci = c0; ci < c0 + 16; ci++) {
            sin[ci][px]     = bsample(y2p + (size_t)ci*HW, s2);   // a2
            sin[C + ci][px] = bsample(y1p + (size_t)ci*HW, s1);   // a1
        }
    }
    __syncthreads();

    // ---- phase B: 1x1 conv; thread = 4 cols x 4 oc ----
    int tx = tid & 7;                    // cols 4tx..4tx+3
    int og = tid >> 3;                   // oc group 0..15 (oc 4og..4og+3)

    const float* xb = feats + (size_t)(n*T + t) * C * HW + y*W + x0;

    float4 acc[4];
    #pragma unroll
    for (int o = 0; o < 4; o++) {
        float b = __ldg(bfc + og*4 + o);
        acc[o] = make_float4(b, b, b, b);
    }

    #pragma unroll 4
    for (int c = 0; c < 2*C; c++) {
        float4 v = *((const float4*)&sin[c][0] + tx);
        float4 wv = __ldg((const float4*)(g_wfc_t + (size_t)c * C) + og);
        float wo[4] = {wv.x, wv.y, wv.z, wv.w};
        #pragma unroll
        for (int o = 0; o < 4; o++) {
            acc[o].x += v.x*wo[o]; acc[o].y += v.y*wo[o];
            acc[o].z += v.z*wo[o]; acc[o].w += v.w*wo[o];
        }
    }
    #pragma unroll 4
    for (int c = 0; c < C; c++) {
        float4 v = __ldg((const float4*)(xb + (size_t)c*HW) + tx);
        float4 wv = __ldg((const float4*)(g_wfc_t + (size_t)(2*C + c) * C) + og);
        float wo[4] = {wv.x, wv.y, wv.z, wv.w};
        #pragma unroll
        for (int o = 0; o < 4; o++) {
            acc[o].x += v.x*wo[o]; acc[o].y += v.y*wo[o];
            acc[o].z += v.z*wo[o]; acc[o].w += v.w*wo[o];
        }
    }

    float* ob = g_infeat + (size_t)n * C * HW + y*W + x0 + 4*tx;
    #pragma unroll
    for (int o = 0; o < 4; o++)
        *((float4*)(ob + (size_t)(og*4+o)*HW)) = acc[o];
}

// ---------------- kernels 2/3: 3x3 conv, 64->64, SAME, zero pad ----------------
// grid (4, 8, NB*16), block 64 (8tx x 8ty); tile 32x16
// thread = 4 cols x 2 rows x 4 oc; cp.async double-buffered input stages;
// weights staged in smem (broadcast LDS)
// phase 0: g_infeat -> leaky_relu -> g_h1
// phase 1: g_h1 -> + feats[t] -> d_out[t]
__global__ __launch_bounds__(64, 7) void k_conv3(
    float* __restrict__ outp, const float* __restrict__ bias,
    const float* __restrict__ feats, int phase, int t)
{
    __shared__ float s[2][CH4][18][36];        // 20736 B (2 stages)
    __shared__ float4 wsm[C*9];                // 9216 B: [(ci*9+k)] -> this ocg's 4 oc
    int n   = blockIdx.z >> 4;
    int ocg = blockIdx.z & 15;                 // 4 oc per group
    int gx0 = blockIdx.x * 32 - 1;             // halo origin
    int gy0 = blockIdx.y * 16 - 1;
    int tid = threadIdx.x;
    int tx = tid & 7;                          // cols 4tx..4tx+3 (output)
    int ty = tid >> 3;                         // 0..7 -> output rows 2ty, 2ty+1

    const float* inb = (phase ? g_h1 : g_infeat) + (size_t)n * C * HW;
    const float* wt  = phase ? g_w2_t : g_w1_t;

    // ---- stage this ocg's weights into smem (9 float4 loads/thread) ----
    for (int i = tid; i < C*9; i += 64)
        wsm[i] = __ldg((const float4*)(wt + (size_t)i * C) + ocg);

    // ---- precompute fill tables: 10 positions/thread, no div in hot loop ----
    bool finA[10], fvdA[10];
    int  gofA[10], sofA[10];
    #pragma unroll
    for (int q = 0; q < 10; q++) {
        int p = tid + q*64;
        bool inr = (p < 18*34);
        int ry = p / 34, rx = p - ry*34;
        int gy = gy0 + ry, gx = gx0 + rx;
        finA[q] = inr;
        bool vd = inr && (gy >= 0) && (gy < H) && (gx >= 0) && (gx < W);
        fvdA[q] = vd;
        gofA[q] = vd ? (gy*W + gx) : 0;
        sofA[q] = ry*36 + rx;
    }
    uint32_t s_u32 = smem_u32(&s[0][0][0][0]);

    float4 acc[2][4];                          // [row][oc], lanes = 4 cols
    #pragma unroll
    for (int o = 0; o < 4; o++) {
        float b = __ldg(bias + ocg*4 + o);
        acc[0][o] = make_float4(b, b, b, b);
        acc[1][o] = acc[0][o];
    }

    // ---- async fill of one stage ----
    auto fill = [&](int st, int cc) {
        const float* cb = inb + (size_t)cc * HW;
        uint32_t sb = s_u32 + (uint32_t)st * (STG_F*4);
        #pragma unroll
        for (int q = 0; q < 10; q++) {
            if (finA[q]) {
                uint32_t sa = sb + (uint32_t)sofA[q]*4;
                const float* g = cb + gofA[q];
                #pragma unroll
                for (int ci = 0; ci < CH4; ci++)
                    cp4(sa + ci*(18*36*4), g + (size_t)ci*HW, fvdA[q]);
            }
        }
    };

    fill(0, 0); CP_COMMIT();

    for (int k = 0; k < C/CH4; k++) {
        int cur = k & 1;
        int cc = k * CH4;
        if (k < C/CH4 - 1) { fill(cur ^ 1, cc + CH4); CP_COMMIT(); CP_WAIT1(); }
        else               { CP_WAIT0(); }
        __syncthreads();

        #pragma unroll
        for (int ci = 0; ci < CH4; ci++) {
            // taps: 4 rows (2ty..2ty+3) x 8 cols, 2 LDS.128 per row
            float ta[4][8];
            const float4* s4 = (const float4*)&s[cur][ci][0][0];  // row stride = 9 float4
            #pragma unroll
            for (int r = 0; r < 4; r++) {
                float4 a = s4[(2*ty + r)*9 + tx];
                float4 b = s4[(2*ty + r)*9 + tx + 1];
                ta[r][0]=a.x; ta[r][1]=a.y; ta[r][2]=a.z; ta[r][3]=a.w;
                ta[r][4]=b.x; ta[r][5]=b.y; ta[r][6]=b.z; ta[r][7]=b.w;
            }
            #pragma unroll
            for (int ky = 0; ky < 3; ky++) {
                #pragma unroll
                for (int kx = 0; kx < 3; kx++) {
                    float4 wv = wsm[(cc+ci)*9 + ky*3 + kx];
                    float wo[4] = {wv.x, wv.y, wv.z, wv.w};
                    #pragma unroll
                    for (int pr = 0; pr < 2; pr++) {
                        #pragma unroll
                        for (int o = 0; o < 4; o++) {
                            acc[pr][o].x += ta[pr+ky][kx+0]*wo[o];
                            acc[pr][o].y += ta[pr+ky][kx+1]*wo[o];
                            acc[pr][o].z += ta[pr+ky][kx+2]*wo[o];
                            acc[pr][o].w += ta[pr+ky][kx+3]*wo[o];
                        }
                    }
                }
            }
        }
        __syncthreads();
    }

    int xo = blockIdx.x*32 + 4*tx;
    int yo = blockIdx.y*16 + 2*ty;
    int p0 = yo * W + xo;
    int p1 = p0 + W;

    if (phase == 0) {
        float* ob = g_h1 + (size_t)n * C * HW;
        #pragma unroll
        for (int o = 0; o < 4; o++) {
            float4 a = acc[0][o], b = acc[1][o];
            a.x = a.x > 0.f ? a.x : 0.1f*a.x;  a.y = a.y > 0.f ? a.y : 0.1f*a.y;
            a.z = a.z > 0.f ? a.z : 0.1f*a.z;  a.w = a.w > 0.f ? a.w : 0.1f*a.w;
            b.x = b.x > 0.f ? b.x : 0.1f*b.x;  b.y = b.y > 0.f ? b.y : 0.1f*b.y;
            b.z = b.z > 0.f ? b.z : 0.1f*b.z;  b.w = b.w > 0.f ? b.w : 0.1f*b.w;
            *((float4*)(ob + (size_t)(ocg*4+o)*HW + p0)) = a;
            *((float4*)(ob + (size_t)(ocg*4+o)*HW + p1)) = b;
        }
    } else {
        size_t base = (size_t)(n*T + t) * C * HW;
        const float* res = feats + base;
        float*       ob  = outp  + base;
        #pragma unroll
        for (int o = 0; o < 4; o++) {
            size_t ch = (size_t)(ocg*4+o)*HW;
            float4 r0 = __ldg((const float4*)(res + ch + p0));
            float4 r1 = __ldg((const float4*)(res + ch + p1));
            float4 a = acc[0][o], b = acc[1][o];
            a.x += r0.x; a.y += r0.y; a.z += r0.z; a.w += r0.w;
            b.x += r1.x; b.y += r1.y; b.z += r1.z; b.w += r1.w;
            *((float4*)(ob + ch + p0)) = a;
            *((float4*)(ob + ch + p1)) = b;
        }
    }
}

// ---------------- launch ----------------
extern "C" void kernel_launch(void* const* d_in, const int* in_sizes, int n_in,
                              void* d_out, int out_size) {
    const float* feats = (const float*)d_in[0];
    const float* flows = (const float*)d_in[1];
    const float* bfc   = (const float*)d_in[3];
    const float* b1    = (const float*)d_in[5];
    const float* b2    = (const float*)d_in[7];
    float* out = (float*)d_out;
    (void)in_sizes; (void)n_in; (void)out_size;

    k_prep<<<(C*9*C + 255)/256, 256>>>((const float*)d_in[2],
                                       (const float*)d_in[4],
                                       (const float*)d_in[6]);

    dim3 cgrid(4, 8, NB*16);
    for (int t = 0; t < T; t++) {
        k_wfc<<<NB*512, 128>>>(feats, flows, out, bfc, t);
        k_conv3<<<cgrid, 64>>>(out, b1, feats, 0, t);
        k_conv3<<<cgrid, 64>>>(out, b2, feats, 1, t);
    }
}

// round 14
// speedup vs baseline: 4.3902x; 1.5418x over previous
#include <cuda_runtime.h>
#include <cuda_bf16.h>
#include <cstdint>

#define NB 2
#define T  16
#define C  64
#define H  128
#define W  128
#define HW (H*W)

typedef __nv_bfloat16 bf16;

// ---------------- scratch (no allocation allowed) ----------------
// activations: pixel-row-major, 128 bf16/pixel = [hi ch0..63 | lo ch0..63]
__device__ __align__(16) bf16 g_fbuf[(size_t)NB*H*W*128];   // 1x1-conv out (conv1 in)
__device__ __align__(16) bf16 g_hbuf[(size_t)NB*H*W*128];   // conv1 out (conv2 in)
__device__ float g_wfc_t[3*C*C];                            // [192][64] fp32
// conv weights: [shift s][oc][ whi(ci 0..63) | wlo(ci 0..63) ]
__device__ __align__(16) bf16 g_w1bf[9*C*128];
__device__ __align__(16) bf16 g_w2bf[9*C*128];

// ---------------- helpers ----------------
__device__ __forceinline__ uint32_t smem_u32(const void* p) {
    uint32_t a;
    asm("{ .reg .u64 t; cvta.to.shared.u64 t, %1; cvt.u32.u64 %0, t; }" : "=r"(a) : "l"(p));
    return a;
}
__device__ __forceinline__ void ldsm4(uint32_t& r0, uint32_t& r1, uint32_t& r2, uint32_t& r3,
                                      uint32_t addr) {
    asm volatile("ldmatrix.sync.aligned.m8n8.x4.shared.b16 {%0,%1,%2,%3}, [%4];"
                 : "=r"(r0), "=r"(r1), "=r"(r2), "=r"(r3) : "r"(addr));
}
__device__ __forceinline__ void mma16816(float* d,
        uint32_t a0, uint32_t a1, uint32_t a2, uint32_t a3, uint32_t b0, uint32_t b1) {
    asm volatile("mma.sync.aligned.m16n8k16.row.col.f32.bf16.bf16.f32 "
                 "{%0,%1,%2,%3}, {%4,%5,%6,%7}, {%8,%9}, {%0,%1,%2,%3};"
                 : "+f"(d[0]), "+f"(d[1]), "+f"(d[2]), "+f"(d[3])
                 : "r"(a0), "r"(a1), "r"(a2), "r"(a3), "r"(b0), "r"(b1));
}
__device__ __forceinline__ uint32_t pk2(float a, float b) {
    return (uint32_t)__bfloat16_as_ushort(__float2bfloat16_rn(a)) |
           ((uint32_t)__bfloat16_as_ushort(__float2bfloat16_rn(b)) << 16);
}
__device__ __forceinline__ float blo(float v) {
    return v - __bfloat162float(__float2bfloat16_rn(v));
}

// ---------------- weight prep ----------------
__global__ void k_prep(const float* __restrict__ Wfc,
                       const float* __restrict__ W1,
                       const float* __restrict__ W2) {
    int i = blockIdx.x * blockDim.x + threadIdx.x;
    if (i < 3*C*C) {
        int c = i >> 6, oc = i & 63;
        g_wfc_t[i] = Wfc[oc * (3*C) + c];
    }
    if (i < 9*C*C) {
        int s = i >> 12, r = i & 4095;
        int oc = r >> 6, ci = r & 63;
        float w1 = W1[(oc*C + ci)*9 + s];
        float w2 = W2[(oc*C + ci)*9 + s];
        bf16 h1 = __float2bfloat16_rn(w1), h2 = __float2bfloat16_rn(w2);
        g_w1bf[(size_t)s*8192 + oc*128 + ci]      = h1;
        g_w1bf[(size_t)s*8192 + oc*128 + 64 + ci] = __float2bfloat16_rn(w1 - __bfloat162float(h1));
        g_w2bf[(size_t)s*8192 + oc*128 + ci]      = h2;
        g_w2bf[(size_t)s*8192 + oc*128 + 64 + ci] = __float2bfloat16_rn(w2 - __bfloat162float(h2));
    }
}

// ---------------- bilinear ----------------
struct Samp { int o00, o01, o10, o11; float w00, w01, w10, w11; };
__device__ __forceinline__ Samp make_samp(float gx, float gy) {
    float x0f = floorf(gx), y0f = floorf(gy);
    float wx = gx - x0f, wy = gy - y0f;
    int x0 = (int)x0f, y0 = (int)y0f, x1 = x0 + 1, y1 = y0 + 1;
    bool vx0 = (x0>=0)&&(x0<W), vx1 = (x1>=0)&&(x1<W);
    bool vy0 = (y0>=0)&&(y0<H), vy1 = (y1>=0)&&(y1<H);
    int cx0 = min(max(x0,0),W-1), cx1 = min(max(x1,0),W-1);
    int cy0 = min(max(y0,0),H-1), cy1 = min(max(y1,0),H-1);
    Samp s;
    s.o00 = cy0*W+cx0; s.o01 = cy0*W+cx1; s.o10 = cy1*W+cx0; s.o11 = cy1*W+cx1;
    s.w00 = (vx0&&vy0) ? (1.f-wx)*(1.f-wy) : 0.f;
    s.w01 = (vx1&&vy0) ? wx*(1.f-wy)       : 0.f;
    s.w10 = (vx0&&vy1) ? (1.f-wx)*wy       : 0.f;
    s.w11 = (vx1&&vy1) ? wx*wy             : 0.f;
    return s;
}
__device__ __forceinline__ float bsample(const float* __restrict__ p, const Samp& s) {
    return p[s.o00]*s.w00 + p[s.o01]*s.w01 + p[s.o10]*s.w10 + p[s.o11]*s.w11;
}

// ---------------- kernel 1: fused warp + 1x1 conv, split-bf16 row epilogue ----------------
__global__ __launch_bounds__(128) void k_wfc(
    const float* __restrict__ feats, const float* __restrict__ flows,
    const float* __restrict__ out,   const float* __restrict__ bfc, int t)
{
    __shared__ float sin[2*C][32];
    __shared__ Samp ss1[32], ss2[32];

    int bid = blockIdx.x;
    int n = bid >> 9, rem = bid & 511;
    int y = rem >> 2, x0 = (rem & 3) * 32;
    int tid = threadIdx.x;

    const float* y1p = (t >= 1) ? out   + (size_t)(n*T + (t-1)) * C * HW
                                : feats + (size_t)(n*T)         * C * HW;
    const float* y2p = (t >= 2) ? out   + (size_t)(n*T + (t-2)) * C * HW
                                : feats + (size_t)(n*T)         * C * HW;

    if (tid < 32) {
        int x = x0 + tid, pix = y * W + x;
        float f1x = 0.f, f1y = 0.f;
        if (t >= 1) {
            const float* f1p = flows + (size_t)(n*T + (t-1)) * 2 * HW;
            f1x = f1p[pix]; f1y = f1p[HW + pix];
        }
        Samp s1 = make_samp((float)x + f1x, (float)y + f1y);
        float f2cx = f1x, f2cy = f1y;
        if (t >= 2) {
            const float* f2p = flows + (size_t)(n*T + (t-2)) * 2 * HW;
            f2cx += bsample(f2p, s1);
            f2cy += bsample(f2p + HW, s1);
        }
        ss1[tid] = s1;
        ss2[tid] = make_samp((float)x + f2cx, (float)y + f2cy);
    }
    __syncthreads();
    {
        int px = tid & 31, cg = tid >> 5;
        Samp s1 = ss1[px], s2 = ss2[px];
        int c0 = cg * 16;
        #pragma unroll 4
        for (int ci = c0; ci < c0 + 16; ci++) {
            sin[ci][px]     = bsample(y2p + (size_t)ci*HW, s2);
            sin[C + ci][px] = bsample(y1p + (size_t)ci*HW, s1);
        }
    }
    __syncthreads();

    int tx = tid & 7, og = tid >> 3;
    const float* xb = feats + (size_t)(n*T + t) * C * HW + y*W + x0;

    float4 acc[4];
    #pragma unroll
    for (int o = 0; o < 4; o++) {
        float b = __ldg(bfc + og*4 + o);
        acc[o] = make_float4(b, b, b, b);
    }
    #pragma unroll 4
    for (int c = 0; c < 2*C; c++) {
        float4 v = *((const float4*)&sin[c][0] + tx);
        float4 wv = __ldg((const float4*)(g_wfc_t + (size_t)c * C) + og);
        float wo[4] = {wv.x, wv.y, wv.z, wv.w};
        #pragma unroll
        for (int o = 0; o < 4; o++) {
            acc[o].x += v.x*wo[o]; acc[o].y += v.y*wo[o];
            acc[o].z += v.z*wo[o]; acc[o].w += v.w*wo[o];
        }
    }
    #pragma unroll 4
    for (int c = 0; c < C; c++) {
        float4 v = __ldg((const float4*)(xb + (size_t)c*HW) + tx);
        float4 wv = __ldg((const float4*)(g_wfc_t + (size_t)(2*C + c) * C) + og);
        float wo[4] = {wv.x, wv.y, wv.z, wv.w};
        #pragma unroll
        for (int o = 0; o < 4; o++) {
            acc[o].x += v.x*wo[o]; acc[o].y += v.y*wo[o];
            acc[o].z += v.z*wo[o]; acc[o].w += v.w*wo[o];
        }
    }

    float vj[4][4] = {
        {acc[0].x, acc[1].x, acc[2].x, acc[3].x},
        {acc[0].y, acc[1].y, acc[2].y, acc[3].y},
        {acc[0].z, acc[1].z, acc[2].z, acc[3].z},
        {acc[0].w, acc[1].w, acc[2].w, acc[3].w}};
    #pragma unroll
    for (int j = 0; j < 4; j++) {
        bf16* row = g_fbuf + ((size_t)(n*H + y)*W + x0 + 4*tx + j) * 128;
        float v0 = vj[j][0], v1 = vj[j][1], v2 = vj[j][2], v3 = vj[j][3];
        *((uint2*)(row + og*4))      = make_uint2(pk2(v0, v1), pk2(v2, v3));
        *((uint2*)(row + 64 + og*4)) = make_uint2(pk2(blo(v0), blo(v1)), pk2(blo(v2), blo(v3)));
    }
}

// ---------------- 3x3 conv via mma.sync bf16 (split 3-term), 9 shifted K=192 GEMMs ----
// grid (2, 128, NB), block 128 (4 warps); CTA = 64-px row strip x 64 oc
#define AROW 136
#define ASZ  (3*66*AROW)
#define BSZ  (64*AROW)
#define SMEM_CONV ((ASZ + BSZ) * 2)

__global__ __launch_bounds__(128) void k_conv_mma(
    float* __restrict__ outp, const float* __restrict__ bias,
    const float* __restrict__ feats, int phase, int t)
{
    extern __shared__ __align__(16) uint8_t smraw[];
    bf16*  As = (bf16*)smraw;              // [3][66][AROW]
    bf16*  Bs = (bf16*)smraw + ASZ;        // [64][AROW]
    float* Ds = (float*)smraw;             // epilogue reuse: [64][66]

    int tid = threadIdx.x, lane = tid & 31, warp = tid >> 5;
    int n = blockIdx.z, y = blockIdx.y, x0 = blockIdx.x * 64;

    const bf16* act  = phase ? g_hbuf : g_fbuf;
    const bf16* wsrc = phase ? g_w2bf : g_w1bf;

    // ---- stage A: rows y-1..y+1, cols x0-1..x0+64, 128 bf16 each ----
    for (int i = tid; i < 3*66*16; i += 128) {
        int u = i & 15, cc = (i >> 4) % 66, r = (i >> 4) / 66;
        int gy = y + r - 1, gx = x0 + cc - 1;
        uint4 v = make_uint4(0u, 0u, 0u, 0u);
        if (gy >= 0 && gy < H && gx >= 0 && gx < W)
            v = __ldg((const uint4*)(act + ((size_t)(n*H + gy)*W + gx)*128) + u);
        *((uint4*)(As + (r*66 + cc)*AROW) + u) = v;
    }

    float ac[8][4];
    #pragma unroll
    for (int nf = 0; nf < 8; nf++) {
        ac[nf][0] = 0.f; ac[nf][1] = 0.f; ac[nf][2] = 0.f; ac[nf][3] = 0.f;
    }

    uint32_t as_u32 = smem_u32(As);
    uint32_t bs_u32 = smem_u32(Bs);
    int a_px = ((lane >> 3) & 1)*8 + (lane & 7);
    int a_k8 = (lane >> 4) * 8;
    int b_oc = ((lane >> 4) & 1)*8 + (lane & 7);
    int b_k8 = ((lane >> 3) & 1)*8;

    const int a_offs[12] = {0,16,32,48, 64,80,96,112, 0,16,32,48};
    const int b_offs[12] = {0,16,32,48, 0,16,32,48, 64,80,96,112};

    for (int s = 0; s < 9; s++) {
        __syncthreads();
        for (int i = tid; i < 64*16; i += 128) {          // stage B for shift s
            int u = i & 15, oc = i >> 4;
            *((uint4*)(Bs + oc*AROW) + u) =
                __ldg((const uint4*)(wsrc + ((size_t)s*64 + oc)*128) + u);
        }
        __syncthreads();

        int r = s / 3, dx = (s % 3) - 1;
        uint32_t abase = as_u32 +
            (uint32_t)((r*66 + warp*16 + a_px + dx + 1)*AROW + a_k8) * 2;
        uint32_t bbase = bs_u32 + (uint32_t)(b_oc*AROW + b_k8) * 2;

        #pragma unroll
        for (int j = 0; j < 12; j++) {
            uint32_t a0, a1, a2, a3;
            ldsm4(a0, a1, a2, a3, abase + a_offs[j]*2);
            #pragma unroll
            for (int e2 = 0; e2 < 4; e2++) {
                uint32_t b0, b1, b2, b3;
                ldsm4(b0, b1, b2, b3, bbase + (e2*16*AROW + b_offs[j])*2);
                mma16816(ac[2*e2],     a0, a1, a2, a3, b0, b1);
                mma16816(ac[2*e2 + 1], a0, a1, a2, a3, b2, b3);
            }
        }
    }

    __syncthreads();
    // ---- fragments -> Ds (bias + activation), then coalesced writeout ----
    int g = lane >> 2, tg = lane & 3;
    int pa = warp*16 + g, pb = pa + 8;
    #pragma unroll
    for (int nf = 0; nf < 8; nf++) {
        int oc = nf*8 + 2*tg;
        float bx = __ldg(bias + oc), by = __ldg(bias + oc + 1);
        float v0 = ac[nf][0] + bx, v1 = ac[nf][1] + by;
        float v2 = ac[nf][2] + bx, v3 = ac[nf][3] + by;
        if (phase == 0) {
            v0 = v0 > 0.f ? v0 : 0.1f*v0;  v1 = v1 > 0.f ? v1 : 0.1f*v1;
            v2 = v2 > 0.f ? v2 : 0.1f*v2;  v3 = v3 > 0.f ? v3 : 0.1f*v3;
        }
        Ds[pa*66 + oc] = v0;  Ds[pa*66 + oc + 1] = v1;
        Ds[pb*66 + oc] = v2;  Ds[pb*66 + oc + 1] = v3;
    }
    __syncthreads();

    if (phase == 0) {
        for (int i = tid; i < 64*16; i += 128) {
            int px = i >> 4, q = i & 15;
            const float* dv = Ds + px*66 + q*4;
            float v0 = dv[0], v1 = dv[1], v2 = dv[2], v3 = dv[3];
            bf16* row = g_hbuf + ((size_t)(n*H + y)*W + x0 + px) * 128;
            *((uint2*)(row + q*4))      = make_uint2(pk2(v0, v1), pk2(v2, v3));
            *((uint2*)(row + 64 + q*4)) = make_uint2(pk2(blo(v0), blo(v1)), pk2(blo(v2), blo(v3)));
        }
    } else {
        size_t base = (size_t)(n*T + t)*C*HW + (size_t)y*W + x0;
        for (int i = tid; i < 64*64; i += 128) {
            int oc = i >> 6, px = i & 63;
            size_t off = base + (size_t)oc*HW + px;
            outp[off] = Ds[px*66 + oc] + __ldg(feats + off);
        }
    }
}

// ---------------- launch ----------------
extern "C" void kernel_launch(void* const* d_in, const int* in_sizes, int n_in,
                              void* d_out, int out_size) {
    const float* feats = (const float*)d_in[0];
    const float* flows = (const float*)d_in[1];
    const float* bfc   = (const float*)d_in[3];
    const float* b1    = (const float*)d_in[5];
    const float* b2    = (const float*)d_in[7];
    float* out = (float*)d_out;
    (void)in_sizes; (void)n_in; (void)out_size;

    cudaFuncSetAttribute(k_conv_mma, cudaFuncAttributeMaxDynamicSharedMemorySize, SMEM_CONV);

    k_prep<<<(9*C*C + 255)/256, 256>>>((const float*)d_in[2],
                                       (const float*)d_in[4],
                                       (const float*)d_in[6]);

    dim3 mgrid(2, 128, NB);
    for (int t = 0; t < T; t++) {
        k_wfc<<<NB*512, 128>>>(feats, flows, out, bfc, t);
        k_conv_mma<<<mgrid, 128, SMEM_CONV>>>(out, b1, feats, 0, t);
        k_conv_mma<<<mgrid, 128, SMEM_CONV>>>(out, b2, feats, 1, t);
    }
}